// round 9
// baseline (speedup 1.0000x reference)
#include <cuda_runtime.h>
#include <cuda_bf16.h>
#include <math.h>

// ---------------- scratch (device globals: allocation-free) ----------------
static __device__ float g_y[52428800];        // conv1 out: (512,256,20,20)  209.7 MB
static __device__ float g_u[4718592];         // u: (512,1152,8)             18.9 MB
static __device__ float g_priors[94371840];   // priors: (512,10,1152,16)    377.5 MB
static __device__ float g_logits[5120];       // (512,10) pre-softmax

// ---------------- conv1: x(512,1,28,28) * w(256,1,9,9) -> y(512,256,20,20) ----------------
// One block per batch image; one thread per output channel (weights in registers).
__global__ void __launch_bounds__(256) conv1_kernel(const float* __restrict__ x,
                                                    const float* __restrict__ w,
                                                    const float* __restrict__ cb) {
    __shared__ float s_img[784];
    int b = blockIdx.x;
    int co = threadIdx.x;
    for (int i = threadIdx.x; i < 784; i += 256) s_img[i] = x[b * 784 + i];
    float wreg[81];
#pragma unroll
    for (int j = 0; j < 81; j++) wreg[j] = w[co * 81 + j];
    float bs = cb[co];
    __syncthreads();
    float* outp = g_y + ((size_t)b * 256 + co) * 400;
    for (int oh = 0; oh < 20; oh++) {
        for (int owg = 0; owg < 20; owg += 4) {
            float a0 = bs, a1 = bs, a2 = bs, a3 = bs;
#pragma unroll
            for (int kh = 0; kh < 9; kh++) {
                const float* ip = &s_img[(oh + kh) * 28 + owg];
#pragma unroll
                for (int kw = 0; kw < 9; kw++) {
                    float wv = wreg[kh * 9 + kw];
                    a0 = fmaf(ip[kw + 0], wv, a0);
                    a1 = fmaf(ip[kw + 1], wv, a1);
                    a2 = fmaf(ip[kw + 2], wv, a2);
                    a3 = fmaf(ip[kw + 3], wv, a3);
                }
            }
            *reinterpret_cast<float4*>(outp + oh * 20 + owg) = make_float4(a0, a1, a2, a3);
        }
    }
}

// ---------------- conv2 as implicit GEMM ----------------
// C[co(256), n(18432)] = W[co, k(20736)] * Patch[k, n]
// k = ci*81 + kh*9 + kw ; n = b*36 + oh*6 + ow ; Patch[k][n] = y[b,ci,2oh+kh,2ow+kw]
// Tiles: BM=64(co) x BN=128(n) x BK=16, 256 threads, 4x8 per-thread tile.
// Epilogue writes directly into u layout: u[b, r=(co%32)*36+pos, d=co/32] = p + bias
__global__ void __launch_bounds__(256) conv2_kernel(const float* __restrict__ w,
                                                    const float* __restrict__ pb) {
    __shared__ float As[16][64];
    __shared__ float Bs[16][128];
    __shared__ int s_nbase[128];
    int tid = threadIdx.x;
    int n0 = blockIdx.x * 128;
    int m0 = blockIdx.y * 64;
    if (tid < 128) {
        int n = n0 + tid;
        int b = n / 36, pos = n - b * 36;
        int oh = pos / 6, ow = pos - oh * 6;
        s_nbase[tid] = b * 102400 + oh * 40 + ow * 2;
    }
    __syncthreads();
    int mg = tid >> 4, ng = tid & 15;
    float acc[4][8];
#pragma unroll
    for (int i = 0; i < 4; i++)
#pragma unroll
        for (int j = 0; j < 8; j++) acc[i][j] = 0.f;

    int a_m = tid >> 2;              // 0..63
    int a_k = (tid & 3) << 2;        // 0,4,8,12
    int b_k = tid >> 4;              // 0..15
    int b_n = (tid & 15) << 3;       // 0..120
    const float* wrow = w + (size_t)(m0 + a_m) * 20736 + a_k;

    for (int k0 = 0; k0 < 20736; k0 += 16) {
        // stage global loads in registers (overlap with previous compute)
        float4 av = *reinterpret_cast<const float4*>(wrow + k0);
        int kk = k0 + b_k;
        int ci = kk / 81;
        int rr = kk - ci * 81;
        int kh = rr / 9;
        int kw = rr - kh * 9;
        int koff = ci * 400 + kh * 20 + kw;
        float bv[8];
#pragma unroll
        for (int j = 0; j < 8; j++) bv[j] = g_y[s_nbase[b_n + j] + koff];

        __syncthreads();
        As[a_k + 0][a_m] = av.x;
        As[a_k + 1][a_m] = av.y;
        As[a_k + 2][a_m] = av.z;
        As[a_k + 3][a_m] = av.w;
#pragma unroll
        for (int j = 0; j < 8; j++) Bs[b_k][b_n + j] = bv[j];
        __syncthreads();

#pragma unroll
        for (int k = 0; k < 16; k++) {
            float4 a4 = *reinterpret_cast<const float4*>(&As[k][mg << 2]);
            float4 b0 = *reinterpret_cast<const float4*>(&Bs[k][ng << 3]);
            float4 b1 = *reinterpret_cast<const float4*>(&Bs[k][(ng << 3) + 4]);
            float ar[4] = {a4.x, a4.y, a4.z, a4.w};
            float br[8] = {b0.x, b0.y, b0.z, b0.w, b1.x, b1.y, b1.z, b1.w};
#pragma unroll
            for (int i = 0; i < 4; i++)
#pragma unroll
                for (int j = 0; j < 8; j++) acc[i][j] = fmaf(ar[i], br[j], acc[i][j]);
        }
    }

#pragma unroll
    for (int i = 0; i < 4; i++) {
        int co = m0 + (mg << 2) + i;
        float bias = pb[co];
        int cm = co & 31, d = co >> 5;
#pragma unroll
        for (int j = 0; j < 8; j++) {
            int n = n0 + (ng << 3) + j;
            int b = n / 36, pos = n - b * 36;
            int r = cm * 36 + pos;
            g_u[((size_t)b * 1152 + r) * 8 + d] = acc[i][j] + bias;
        }
    }
}

// ---------------- squash u in place (per 8-dim capsule vector) ----------------
__global__ void squash_kernel() {
    int idx = blockIdx.x * 256 + threadIdx.x;
    if (idx >= 512 * 1152) return;
    float4 v0 = *reinterpret_cast<float4*>(&g_u[(size_t)idx * 8]);
    float4 v1 = *reinterpret_cast<float4*>(&g_u[(size_t)idx * 8 + 4]);
    float sn = v0.x * v0.x + v0.y * v0.y + v0.z * v0.z + v0.w * v0.w +
               v1.x * v1.x + v1.y * v1.y + v1.z * v1.z + v1.w * v1.w;
    float sc = sqrtf(sn) / (1.f + sn);
    v0.x *= sc; v0.y *= sc; v0.z *= sc; v0.w *= sc;
    v1.x *= sc; v1.y *= sc; v1.z *= sc; v1.w *= sc;
    *reinterpret_cast<float4*>(&g_u[(size_t)idx * 8]) = v0;
    *reinterpret_cast<float4*>(&g_u[(size_t)idx * 8 + 4]) = v1;
}

// ---------------- priors[b,c,r,o] = sum_i u[b,r,i] * route_w[c,r,i,o] ----------------
// Block = (r-chunk of 16, c); route_w slice cached in smem, loop over all b.
__global__ void __launch_bounds__(256) priors_kernel(const float* __restrict__ rw) {
    __shared__ float s_w[2048];   // 16 r x 8 i x 16 o
    __shared__ float s_u[128];    // 16 r x 8 i
    int tid = threadIdx.x;
    int r0 = blockIdx.x * 16;
    int c = blockIdx.y;
    const float* wsrc = rw + (size_t)c * 147456 + (size_t)r0 * 128;
    for (int i = tid; i < 2048; i += 256) s_w[i] = wsrc[i];
    int rl = tid >> 4, o = tid & 15;
    float* pdst = g_priors + (size_t)c * 18432 + (size_t)r0 * 16 + tid;
    for (int b = 0; b < 512; b++) {
        if (tid < 128) s_u[tid] = g_u[(size_t)b * 9216 + r0 * 8 + tid];
        __syncthreads();
        float acc = 0.f;
#pragma unroll
        for (int i = 0; i < 8; i++)
            acc = fmaf(s_u[rl * 8 + i], s_w[rl * 128 + i * 16 + o], acc);
        pdst[(size_t)b * 184320] = acc;
        __syncthreads();
    }
}

// ---------------- routing: one block per (b,c); 3 iterations entirely in smem ----------------
__device__ __forceinline__ float blk_reduce_max(float v, float* red) {
#pragma unroll
    for (int s = 16; s; s >>= 1) v = fmaxf(v, __shfl_xor_sync(0xffffffffu, v, s));
    if ((threadIdx.x & 31) == 0) red[threadIdx.x >> 5] = v;
    __syncthreads();
    float r = red[0];
#pragma unroll
    for (int i = 1; i < 8; i++) r = fmaxf(r, red[i]);
    __syncthreads();
    return r;
}

__device__ __forceinline__ float blk_reduce_sum(float v, float* red) {
#pragma unroll
    for (int s = 16; s; s >>= 1) v += __shfl_xor_sync(0xffffffffu, v, s);
    if ((threadIdx.x & 31) == 0) red[threadIdx.x >> 5] = v;
    __syncthreads();
    float r = red[0];
#pragma unroll
    for (int i = 1; i < 8; i++) r += red[i];
    __syncthreads();
    return r;
}

__global__ void __launch_bounds__(256) routing_kernel() {
    extern __shared__ float sm[];
    float* P     = sm;          // [1152][17] padded (conflict-free) : 19584
    float* blog  = sm + 19584;  // 1152
    float* probs = sm + 20736;  // 1152
    float* sred  = sm + 21888;  // 256
    float* s_s   = sm + 22144;  // 16
    float* s_v   = sm + 22160;  // 16
    float* red   = sm + 22176;  // 8

    int tid = threadIdx.x;
    int b = blockIdx.x, c = blockIdx.y;
    const float* gp = g_priors + ((size_t)b * 10 + c) * 18432;
    for (int idx = tid; idx < 18432; idx += 256) {
        int r = idx >> 4, o = idx & 15;
        P[r * 17 + o] = gp[idx];
    }
    for (int r = tid; r < 1152; r += 256) blog[r] = 0.f;
    __syncthreads();

    int o = tid & 15, rg = tid >> 4;
    for (int it = 0; it < 3; it++) {
        // softmax(blog) over r -> probs (unnormalized; inv applied to s)
        float mx = -1e30f;
        for (int r = tid; r < 1152; r += 256) mx = fmaxf(mx, blog[r]);
        mx = blk_reduce_max(mx, red);
        float se = 0.f;
        for (int r = tid; r < 1152; r += 256) {
            float e = expf(blog[r] - mx);
            probs[r] = e;
            se += e;
        }
        se = blk_reduce_sum(se, red);
        float inv = 1.f / se;

        // s[o] = sum_r probs[r] * P[r][o]
        float acc = 0.f;
        for (int r = rg; r < 1152; r += 16) acc = fmaf(probs[r], P[r * 17 + o], acc);
        sred[tid] = acc;
        __syncthreads();
        if (tid < 16) {
            float s = 0.f;
#pragma unroll
            for (int g = 0; g < 16; g++) s += sred[g * 16 + tid];
            s_s[tid] = s * inv;
        }
        __syncthreads();
        // v = squash(s); logit = |v| = sn/(1+sn)
        if (tid < 16) {
            float sn = 0.f;
#pragma unroll
            for (int oo = 0; oo < 16; oo++) sn += s_s[oo] * s_s[oo];
            float sc = sqrtf(sn) / (1.f + sn);
            s_v[tid] = s_s[tid] * sc;
            if (tid == 0 && it == 2) g_logits[b * 10 + c] = sn / (1.f + sn);
        }
        __syncthreads();
        // blog[r] += sum_o P[r][o] * v[o]  (dead on final iteration)
        if (it < 2) {
            for (int r = tid; r < 1152; r += 256) {
                float a = 0.f;
#pragma unroll
                for (int oo = 0; oo < 16; oo++) a = fmaf(P[r * 17 + oo], s_v[oo], a);
                blog[r] += a;
            }
            __syncthreads();
        }
    }
}

// ---------------- final softmax over 10 classes ----------------
__global__ void final_kernel(float* __restrict__ out) {
    int b = blockIdx.x * blockDim.x + threadIdx.x;
    if (b >= 512) return;
    float l[10];
    float mx = -1e30f;
#pragma unroll
    for (int i = 0; i < 10; i++) { l[i] = g_logits[b * 10 + i]; mx = fmaxf(mx, l[i]); }
    float se = 0.f;
#pragma unroll
    for (int i = 0; i < 10; i++) { l[i] = expf(l[i] - mx); se += l[i]; }
    float inv = 1.f / se;
#pragma unroll
    for (int i = 0; i < 10; i++) out[b * 10 + i] = l[i] * inv;
}

// ---------------- launch ----------------
extern "C" void kernel_launch(void* const* d_in, const int* in_sizes, int n_in,
                              void* d_out, int out_size) {
    const float* x       = (const float*)d_in[0];
    const float* conv_w  = (const float*)d_in[1];
    const float* conv_b  = (const float*)d_in[2];
    const float* prim_w  = (const float*)d_in[3];
    const float* prim_b  = (const float*)d_in[4];
    const float* route_w = (const float*)d_in[5];
    float* out = (float*)d_out;

    conv1_kernel<<<512, 256>>>(x, conv_w, conv_b);
    conv2_kernel<<<dim3(144, 4), 256>>>(prim_w, prim_b);
    squash_kernel<<<2304, 256>>>();
    priors_kernel<<<dim3(72, 10), 256>>>(route_w);
    cudaFuncSetAttribute(routing_kernel, cudaFuncAttributeMaxDynamicSharedMemorySize, 90112);
    routing_kernel<<<dim3(512, 10), 256, 22184 * 4>>>();
    final_kernel<<<2, 256>>>(out);
}

// round 10
// speedup vs baseline: 1.0012x; 1.0012x over previous
#include <cuda_runtime.h>
#include <cuda_bf16.h>
#include <math.h>

// ---------------- scratch (device globals: allocation-free) ----------------
static __device__ float g_y[52428800];        // conv1 out: (512,256,20,20)  209.7 MB
static __device__ float g_u[4718592];         // u: (512,1152,8)             18.9 MB
static __device__ float g_priors[94371840];   // priors: (512,10,1152,16)    377.5 MB
static __device__ float g_logits[5120];       // (512,10) pre-softmax

// ---------------- conv1: x(512,1,28,28) * w(256,1,9,9) -> y(512,256,20,20) ----------------
// One block per batch image; one thread per output channel (weights in registers).
__global__ void __launch_bounds__(256) conv1_kernel(const float* __restrict__ x,
                                                    const float* __restrict__ w,
                                                    const float* __restrict__ cb) {
    __shared__ float s_img[784];
    int b = blockIdx.x;
    int co = threadIdx.x;
    for (int i = threadIdx.x; i < 784; i += 256) s_img[i] = x[b * 784 + i];
    float wreg[81];
#pragma unroll
    for (int j = 0; j < 81; j++) wreg[j] = w[co * 81 + j];
    float bs = cb[co];
    __syncthreads();
    float* outp = g_y + ((size_t)b * 256 + co) * 400;
    for (int oh = 0; oh < 20; oh++) {
        for (int owg = 0; owg < 20; owg += 4) {
            float a0 = bs, a1 = bs, a2 = bs, a3 = bs;
#pragma unroll
            for (int kh = 0; kh < 9; kh++) {
                const float* ip = &s_img[(oh + kh) * 28 + owg];
#pragma unroll
                for (int kw = 0; kw < 9; kw++) {
                    float wv = wreg[kh * 9 + kw];
                    a0 = fmaf(ip[kw + 0], wv, a0);
                    a1 = fmaf(ip[kw + 1], wv, a1);
                    a2 = fmaf(ip[kw + 2], wv, a2);
                    a3 = fmaf(ip[kw + 3], wv, a3);
                }
            }
            *reinterpret_cast<float4*>(outp + oh * 20 + owg) = make_float4(a0, a1, a2, a3);
        }
    }
}

// ---------------- conv2 as implicit GEMM ----------------
// C[co(256), n(18432)] = W[co, k(20736)] * Patch[k, n]
// k = ci*81 + kh*9 + kw ; n = b*36 + oh*6 + ow ; Patch[k][n] = y[b,ci,2oh+kh,2ow+kw]
// Tiles: BM=64(co) x BN=128(n) x BK=16, 256 threads, 4x8 per-thread tile.
// Epilogue writes directly into u layout: u[b, r=(co%32)*36+pos, d=co/32] = p + bias
__global__ void __launch_bounds__(256) conv2_kernel(const float* __restrict__ w,
                                                    const float* __restrict__ pb) {
    __shared__ float As[16][64];
    __shared__ float Bs[16][128];
    __shared__ int s_nbase[128];
    int tid = threadIdx.x;
    int n0 = blockIdx.x * 128;
    int m0 = blockIdx.y * 64;
    if (tid < 128) {
        int n = n0 + tid;
        int b = n / 36, pos = n - b * 36;
        int oh = pos / 6, ow = pos - oh * 6;
        s_nbase[tid] = b * 102400 + oh * 40 + ow * 2;
    }
    __syncthreads();
    int mg = tid >> 4, ng = tid & 15;
    float acc[4][8];
#pragma unroll
    for (int i = 0; i < 4; i++)
#pragma unroll
        for (int j = 0; j < 8; j++) acc[i][j] = 0.f;

    int a_m = tid >> 2;              // 0..63
    int a_k = (tid & 3) << 2;        // 0,4,8,12
    int b_k = tid >> 4;              // 0..15
    int b_n = (tid & 15) << 3;       // 0..120
    const float* wrow = w + (size_t)(m0 + a_m) * 20736 + a_k;

    for (int k0 = 0; k0 < 20736; k0 += 16) {
        // stage global loads in registers (overlap with previous compute)
        float4 av = *reinterpret_cast<const float4*>(wrow + k0);
        int kk = k0 + b_k;
        int ci = kk / 81;
        int rr = kk - ci * 81;
        int kh = rr / 9;
        int kw = rr - kh * 9;
        int koff = ci * 400 + kh * 20 + kw;
        float bv[8];
#pragma unroll
        for (int j = 0; j < 8; j++) bv[j] = g_y[s_nbase[b_n + j] + koff];

        __syncthreads();
        As[a_k + 0][a_m] = av.x;
        As[a_k + 1][a_m] = av.y;
        As[a_k + 2][a_m] = av.z;
        As[a_k + 3][a_m] = av.w;
#pragma unroll
        for (int j = 0; j < 8; j++) Bs[b_k][b_n + j] = bv[j];
        __syncthreads();

#pragma unroll
        for (int k = 0; k < 16; k++) {
            float4 a4 = *reinterpret_cast<const float4*>(&As[k][mg << 2]);
            float4 b0 = *reinterpret_cast<const float4*>(&Bs[k][ng << 3]);
            float4 b1 = *reinterpret_cast<const float4*>(&Bs[k][(ng << 3) + 4]);
            float ar[4] = {a4.x, a4.y, a4.z, a4.w};
            float br[8] = {b0.x, b0.y, b0.z, b0.w, b1.x, b1.y, b1.z, b1.w};
#pragma unroll
            for (int i = 0; i < 4; i++)
#pragma unroll
                for (int j = 0; j < 8; j++) acc[i][j] = fmaf(ar[i], br[j], acc[i][j]);
        }
    }

#pragma unroll
    for (int i = 0; i < 4; i++) {
        int co = m0 + (mg << 2) + i;
        float bias = pb[co];
        int cm = co & 31, d = co >> 5;
#pragma unroll
        for (int j = 0; j < 8; j++) {
            int n = n0 + (ng << 3) + j;
            int b = n / 36, pos = n - b * 36;
            int r = cm * 36 + pos;
            g_u[((size_t)b * 1152 + r) * 8 + d] = acc[i][j] + bias;
        }
    }
}

// ---------------- squash u in place (per 8-dim capsule vector) ----------------
__global__ void squash_kernel() {
    int idx = blockIdx.x * 256 + threadIdx.x;
    if (idx >= 512 * 1152) return;
    float4 v0 = *reinterpret_cast<float4*>(&g_u[(size_t)idx * 8]);
    float4 v1 = *reinterpret_cast<float4*>(&g_u[(size_t)idx * 8 + 4]);
    float sn = v0.x * v0.x + v0.y * v0.y + v0.z * v0.z + v0.w * v0.w +
               v1.x * v1.x + v1.y * v1.y + v1.z * v1.z + v1.w * v1.w;
    float sc = sqrtf(sn) / (1.f + sn);
    v0.x *= sc; v0.y *= sc; v0.z *= sc; v0.w *= sc;
    v1.x *= sc; v1.y *= sc; v1.z *= sc; v1.w *= sc;
    *reinterpret_cast<float4*>(&g_u[(size_t)idx * 8]) = v0;
    *reinterpret_cast<float4*>(&g_u[(size_t)idx * 8 + 4]) = v1;
}

// ---------------- priors[b,c,r,o] = sum_i u[b,r,i] * route_w[c,r,i,o] ----------------
// Block = (r-chunk of 16, c); route_w slice cached in smem, loop over all b.
__global__ void __launch_bounds__(256) priors_kernel(const float* __restrict__ rw) {
    __shared__ float s_w[2048];   // 16 r x 8 i x 16 o
    __shared__ float s_u[128];    // 16 r x 8 i
    int tid = threadIdx.x;
    int r0 = blockIdx.x * 16;
    int c = blockIdx.y;
    const float* wsrc = rw + (size_t)c * 147456 + (size_t)r0 * 128;
    for (int i = tid; i < 2048; i += 256) s_w[i] = wsrc[i];
    int rl = tid >> 4, o = tid & 15;
    float* pdst = g_priors + (size_t)c * 18432 + (size_t)r0 * 16 + tid;
    for (int b = 0; b < 512; b++) {
        if (tid < 128) s_u[tid] = g_u[(size_t)b * 9216 + r0 * 8 + tid];
        __syncthreads();
        float acc = 0.f;
#pragma unroll
        for (int i = 0; i < 8; i++)
            acc = fmaf(s_u[rl * 8 + i], s_w[rl * 128 + i * 16 + o], acc);
        pdst[(size_t)b * 184320] = acc;
        __syncthreads();
    }
}

// ---------------- routing: one block per (b,c); 3 iterations entirely in smem ----------------
__device__ __forceinline__ float blk_reduce_max(float v, float* red) {
#pragma unroll
    for (int s = 16; s; s >>= 1) v = fmaxf(v, __shfl_xor_sync(0xffffffffu, v, s));
    if ((threadIdx.x & 31) == 0) red[threadIdx.x >> 5] = v;
    __syncthreads();
    float r = red[0];
#pragma unroll
    for (int i = 1; i < 8; i++) r = fmaxf(r, red[i]);
    __syncthreads();
    return r;
}

__device__ __forceinline__ float blk_reduce_sum(float v, float* red) {
#pragma unroll
    for (int s = 16; s; s >>= 1) v += __shfl_xor_sync(0xffffffffu, v, s);
    if ((threadIdx.x & 31) == 0) red[threadIdx.x >> 5] = v;
    __syncthreads();
    float r = red[0];
#pragma unroll
    for (int i = 1; i < 8; i++) r += red[i];
    __syncthreads();
    return r;
}

__global__ void __launch_bounds__(256) routing_kernel() {
    extern __shared__ float sm[];
    float* P     = sm;          // [1152][17] padded (conflict-free) : 19584
    float* blog  = sm + 19584;  // 1152
    float* probs = sm + 20736;  // 1152
    float* sred  = sm + 21888;  // 256
    float* s_s   = sm + 22144;  // 16
    float* s_v   = sm + 22160;  // 16
    float* red   = sm + 22176;  // 8

    int tid = threadIdx.x;
    int b = blockIdx.x, c = blockIdx.y;
    const float* gp = g_priors + ((size_t)b * 10 + c) * 18432;
    for (int idx = tid; idx < 18432; idx += 256) {
        int r = idx >> 4, o = idx & 15;
        P[r * 17 + o] = gp[idx];
    }
    for (int r = tid; r < 1152; r += 256) blog[r] = 0.f;
    __syncthreads();

    int o = tid & 15, rg = tid >> 4;
    for (int it = 0; it < 3; it++) {
        // softmax(blog) over r -> probs (unnormalized; inv applied to s)
        float mx = -1e30f;
        for (int r = tid; r < 1152; r += 256) mx = fmaxf(mx, blog[r]);
        mx = blk_reduce_max(mx, red);
        float se = 0.f;
        for (int r = tid; r < 1152; r += 256) {
            float e = expf(blog[r] - mx);
            probs[r] = e;
            se += e;
        }
        se = blk_reduce_sum(se, red);
        float inv = 1.f / se;

        // s[o] = sum_r probs[r] * P[r][o]
        float acc = 0.f;
        for (int r = rg; r < 1152; r += 16) acc = fmaf(probs[r], P[r * 17 + o], acc);
        sred[tid] = acc;
        __syncthreads();
        if (tid < 16) {
            float s = 0.f;
#pragma unroll
            for (int g = 0; g < 16; g++) s += sred[g * 16 + tid];
            s_s[tid] = s * inv;
        }
        __syncthreads();
        // v = squash(s); logit = |v| = sn/(1+sn)
        if (tid < 16) {
            float sn = 0.f;
#pragma unroll
            for (int oo = 0; oo < 16; oo++) sn += s_s[oo] * s_s[oo];
            float sc = sqrtf(sn) / (1.f + sn);
            s_v[tid] = s_s[tid] * sc;
            if (tid == 0 && it == 2) g_logits[b * 10 + c] = sn / (1.f + sn);
        }
        __syncthreads();
        // blog[r] += sum_o P[r][o] * v[o]  (dead on final iteration)
        if (it < 2) {
            for (int r = tid; r < 1152; r += 256) {
                float a = 0.f;
#pragma unroll
                for (int oo = 0; oo < 16; oo++) a = fmaf(P[r * 17 + oo], s_v[oo], a);
                blog[r] += a;
            }
            __syncthreads();
        }
    }
}

// ---------------- final softmax over 10 classes ----------------
__global__ void final_kernel(float* __restrict__ out) {
    int b = blockIdx.x * blockDim.x + threadIdx.x;
    if (b >= 512) return;
    float l[10];
    float mx = -1e30f;
#pragma unroll
    for (int i = 0; i < 10; i++) { l[i] = g_logits[b * 10 + i]; mx = fmaxf(mx, l[i]); }
    float se = 0.f;
#pragma unroll
    for (int i = 0; i < 10; i++) { l[i] = expf(l[i] - mx); se += l[i]; }
    float inv = 1.f / se;
#pragma unroll
    for (int i = 0; i < 10; i++) out[b * 10 + i] = l[i] * inv;
}

// ---------------- launch ----------------
extern "C" void kernel_launch(void* const* d_in, const int* in_sizes, int n_in,
                              void* d_out, int out_size) {
    const float* x       = (const float*)d_in[0];
    const float* conv_w  = (const float*)d_in[1];
    const float* conv_b  = (const float*)d_in[2];
    const float* prim_w  = (const float*)d_in[3];
    const float* prim_b  = (const float*)d_in[4];
    const float* route_w = (const float*)d_in[5];
    float* out = (float*)d_out;

    conv1_kernel<<<512, 256>>>(x, conv_w, conv_b);
    conv2_kernel<<<dim3(144, 4), 256>>>(prim_w, prim_b);
    squash_kernel<<<2304, 256>>>();
    priors_kernel<<<dim3(72, 10), 256>>>(route_w);
    cudaFuncSetAttribute(routing_kernel, cudaFuncAttributeMaxDynamicSharedMemorySize, 90112);
    routing_kernel<<<dim3(512, 10), 256, 22184 * 4>>>();
    final_kernel<<<2, 256>>>(out);
}

// round 13
// speedup vs baseline: 4.5886x; 4.5833x over previous
#include <cuda_runtime.h>
#include <cuda_bf16.h>
#include <math.h>
#include <stdint.h>

// ---------------- scratch (device globals: allocation-free) ----------------
static __device__ uint32_t g_y2[52428800];           // conv1 out packed (bf16 hi | lo<<16): (512,256,20,20)
static __device__ __nv_bfloat16 g_wh[5308416];       // prim_w hi: [256][20736]
static __device__ __nv_bfloat16 g_wl[5308416];       // prim_w lo
static __device__ int g_koff[20736];                 // k -> ci*400 + kh*20 + kw
static __device__ float g_u[4718592];                // u: (512,1152,8)
static __device__ float g_priors[94371840];          // priors: (512,10,1152,16)
static __device__ float g_logits[5120];              // (512,10)

// ---------------- helpers ----------------
__device__ __forceinline__ uint32_t smem_u32(const void* p) {
    uint32_t a;
    asm("{ .reg .u64 t; cvta.to.shared.u64 t, %1; cvt.u32.u64 %0, t; }" : "=r"(a) : "l"(p));
    return a;
}
__device__ __forceinline__ void ldsm4(uint32_t* r, uint32_t addr) {
    asm volatile("ldmatrix.sync.aligned.m8n8.x4.shared.b16 {%0,%1,%2,%3}, [%4];"
                 : "=r"(r[0]), "=r"(r[1]), "=r"(r[2]), "=r"(r[3]) : "r"(addr));
}
__device__ __forceinline__ void mma_bf16(float* c, const uint32_t* a, uint32_t b0, uint32_t b1) {
    asm volatile("mma.sync.aligned.m16n8k16.row.col.f32.bf16.bf16.f32 "
                 "{%0,%1,%2,%3}, {%4,%5,%6,%7}, {%8,%9}, {%0,%1,%2,%3};"
                 : "+f"(c[0]), "+f"(c[1]), "+f"(c[2]), "+f"(c[3])
                 : "r"(a[0]), "r"(a[1]), "r"(a[2]), "r"(a[3]), "r"(b0), "r"(b1));
}
__device__ __forceinline__ void cp_async16(uint32_t saddr, const void* gaddr) {
    asm volatile("cp.async.cg.shared.global [%0], [%1], 16;" :: "r"(saddr), "l"(gaddr));
}
__device__ __forceinline__ void cp_commit() { asm volatile("cp.async.commit_group;"); }
__device__ __forceinline__ void cp_wait0() { asm volatile("cp.async.wait_group 0;" ::: "memory"); }
__device__ __forceinline__ uint32_t pack_split(float a) {
    __nv_bfloat16 h = __float2bfloat16(a);
    __nv_bfloat16 l = __float2bfloat16(a - __bfloat162float(h));
    return (uint32_t)__bfloat16_as_ushort(h) | ((uint32_t)__bfloat16_as_ushort(l) << 16);
}

// ---------------- conv1: x(512,1,28,28) * w(256,1,9,9) -> g_y2 packed ----------------
__global__ void __launch_bounds__(256) conv1_kernel(const float* __restrict__ x,
                                                    const float* __restrict__ w,
                                                    const float* __restrict__ cb) {
    __shared__ float s_img[784];
    int b = blockIdx.x;
    int co = threadIdx.x;
    for (int i = threadIdx.x; i < 784; i += 256) s_img[i] = x[b * 784 + i];
    float wreg[81];
#pragma unroll
    for (int j = 0; j < 81; j++) wreg[j] = w[co * 81 + j];
    float bs = cb[co];
    __syncthreads();
    uint32_t* outp = g_y2 + ((size_t)b * 256 + co) * 400;
    for (int oh = 0; oh < 20; oh++) {
        for (int owg = 0; owg < 20; owg += 4) {
            float a0 = bs, a1 = bs, a2 = bs, a3 = bs;
#pragma unroll
            for (int kh = 0; kh < 9; kh++) {
                const float* ip = &s_img[(oh + kh) * 28 + owg];
#pragma unroll
                for (int kw = 0; kw < 9; kw++) {
                    float wv = wreg[kh * 9 + kw];
                    a0 = fmaf(ip[kw + 0], wv, a0);
                    a1 = fmaf(ip[kw + 1], wv, a1);
                    a2 = fmaf(ip[kw + 2], wv, a2);
                    a3 = fmaf(ip[kw + 3], wv, a3);
                }
            }
            uint4 pk = make_uint4(pack_split(a0), pack_split(a1), pack_split(a2), pack_split(a3));
            *reinterpret_cast<uint4*>(outp + oh * 20 + owg) = pk;
        }
    }
}

// ---------------- split prim_w into bf16 hi/lo + build koff table ----------------
__global__ void wsplit_kernel(const float* __restrict__ w) {
    int i = blockIdx.x * 256 + threadIdx.x;
    if (i < 5308416) {
        float v = w[i];
        __nv_bfloat16 h = __float2bfloat16(v);
        __nv_bfloat16 l = __float2bfloat16(v - __bfloat162float(h));
        g_wh[i] = h;
        g_wl[i] = l;
    }
    if (i < 20736) {
        int ci = i / 81, rr = i - ci * 81, kh = rr / 9, kw = rr - kh * 9;
        g_koff[i] = ci * 400 + kh * 20 + kw;
    }
}

// ---------------- conv2 via warp-MMA split-bf16 implicit GEMM ----------------
// C[n(18432), co(256)] = sum_k Patch[n,k] * W[co,k]; 3 mma passes AhBh+AhBl+AlBh.
// CTA tile 128(n) x 128(co), BK=64. 8 warps (4 m x 2 n), warp tile 32x64.
// smem per stage: Ah/Al/Bh/Bl each 128 rows x 144B (64 bf16 + pad) = 4*18432 = 73728B.
#define A_STRIDE 144
#define STAGE_BYTES 73728
__global__ void __launch_bounds__(256, 1) conv2_mma_kernel(const float* __restrict__ pb) {
    extern __shared__ char smc[];
    int* s_nbase = (int*)smc;                 // [128]
    float* s_bias = (float*)(smc + 512);      // [128] (local co)
    char* tiles = smc + 1536;
    uint32_t sTiles = smem_u32(tiles);

    int tid = threadIdx.x, lane = tid & 31, wid = tid >> 5;
    int n0 = blockIdx.x * 128;
    int co0 = blockIdx.y * 128;

    if (tid < 128) {
        int n = n0 + tid;
        int b = n / 36, pos = n - b * 36;
        int oh = pos / 6, ow = pos - oh * 6;
        s_nbase[tid] = b * 102400 + oh * 40 + ow * 2;
        s_bias[tid] = pb[co0 + tid];
    }
    __syncthreads();

    // ---- producer mappings ----
    // A gather: kp = tid&31 covers k = 2kp,2kp+1 ; rows = (tid>>5) + 8j, j=0..15
    int kp = tid & 31;
    int rowb = tid >> 5;
    // B cp.async: chunk c = tid&7 (16B), row r0 = tid>>3 (+32*rr)
    int bchunk = tid & 7;
    int brow0 = tid >> 3;

    // ---- ldmatrix per-thread base offsets (relative to stage base) ----
    int warp_m = wid >> 1, warp_n = wid & 1;
    uint32_t a_off = (uint32_t)(warp_m * 32 + (lane & 7) + ((lane >> 3) & 1) * 8) * A_STRIDE
                     + (uint32_t)(lane >> 4) * 16;
    uint32_t b_off = (uint32_t)(warp_n * 64 + (lane & 7) + ((lane >> 4) & 1) * 8) * A_STRIDE
                     + (uint32_t)((lane >> 3) & 1) * 16;

    float acc[2][8][4];
#pragma unroll
    for (int m = 0; m < 2; m++)
#pragma unroll
        for (int nf = 0; nf < 8; nf++)
#pragma unroll
            for (int e = 0; e < 4; e++) acc[m][nf][e] = 0.f;

    // ---- producer lambdas (expressed inline) ----
    uint32_t va[16], vb[16];

    // prologue: stage 0
    {
        char* stg = tiles;
        // B cp.async (both planes)
#pragma unroll
        for (int rr = 0; rr < 4; rr++) {
            int row = brow0 + rr * 32;
            size_t g = (size_t)(co0 + row) * 41472 + (size_t)bchunk * 16;
            uint32_t so = (uint32_t)row * A_STRIDE + (uint32_t)bchunk * 16;
            cp_async16(sTiles + 36864 + so, (const char*)g_wh + g);
            cp_async16(sTiles + 55296 + so, (const char*)g_wl + g);
        }
        cp_commit();
        int koff0 = g_koff[2 * kp];
        int koff1 = g_koff[2 * kp + 1];
#pragma unroll
        for (int j = 0; j < 16; j++) {
            int nb = s_nbase[rowb + 8 * j];
            va[j] = g_y2[nb + koff0];
            vb[j] = g_y2[nb + koff1];
        }
#pragma unroll
        for (int j = 0; j < 16; j++) {
            uint32_t hp = __byte_perm(va[j], vb[j], 0x5410);
            uint32_t lp = __byte_perm(va[j], vb[j], 0x7632);
            uint32_t so = (uint32_t)(rowb + 8 * j) * A_STRIDE + (uint32_t)kp * 4;
            *(uint32_t*)(stg + so) = hp;
            *(uint32_t*)(stg + 18432 + so) = lp;
        }
        cp_wait0();
        __syncthreads();
    }

    for (int c = 0; c < 324; c++) {
        int s = c & 1;
        uint32_t stage = sTiles + (uint32_t)s * STAGE_BYTES;
        bool pre = (c + 1) < 324;

        if (pre) {
            int k0n = (c + 1) * 64;
            uint32_t nstage = sTiles + (uint32_t)((s ^ 1)) * STAGE_BYTES;
#pragma unroll
            for (int rr = 0; rr < 4; rr++) {
                int row = brow0 + rr * 32;
                size_t g = (size_t)(co0 + row) * 41472 + (size_t)k0n * 2 + (size_t)bchunk * 16;
                uint32_t so = (uint32_t)row * A_STRIDE + (uint32_t)bchunk * 16;
                cp_async16(nstage + 36864 + so, (const char*)g_wh + g);
                cp_async16(nstage + 55296 + so, (const char*)g_wl + g);
            }
            cp_commit();
            int koff0 = g_koff[k0n + 2 * kp];
            int koff1 = g_koff[k0n + 2 * kp + 1];
#pragma unroll
            for (int j = 0; j < 16; j++) {
                int nb = s_nbase[rowb + 8 * j];
                va[j] = g_y2[nb + koff0];
                vb[j] = g_y2[nb + koff1];
            }
        }

        // ---- compute current stage ----
#pragma unroll
        for (int ks = 0; ks < 4; ks++) {
            uint32_t ko = (uint32_t)ks * 32;
            uint32_t ah0[4], ah1[4], al0[4], al1[4];
            ldsm4(ah0, stage + a_off + ko);
            ldsm4(ah1, stage + a_off + 16 * A_STRIDE + ko);
            ldsm4(al0, stage + 18432 + a_off + ko);
            ldsm4(al1, stage + 18432 + a_off + 16 * A_STRIDE + ko);
#pragma unroll
            for (int jj = 0; jj < 4; jj++) {
                uint32_t bh[4], bl[4];
                ldsm4(bh, stage + 36864 + b_off + (uint32_t)jj * (16 * A_STRIDE) + ko);
                ldsm4(bl, stage + 55296 + b_off + (uint32_t)jj * (16 * A_STRIDE) + ko);
                mma_bf16(acc[0][2 * jj],     ah0, bh[0], bh[1]);
                mma_bf16(acc[1][2 * jj],     ah1, bh[0], bh[1]);
                mma_bf16(acc[0][2 * jj + 1], ah0, bh[2], bh[3]);
                mma_bf16(acc[1][2 * jj + 1], ah1, bh[2], bh[3]);
                mma_bf16(acc[0][2 * jj],     ah0, bl[0], bl[1]);
                mma_bf16(acc[1][2 * jj],     ah1, bl[0], bl[1]);
                mma_bf16(acc[0][2 * jj + 1], ah0, bl[2], bl[3]);
                mma_bf16(acc[1][2 * jj + 1], ah1, bl[2], bl[3]);
                mma_bf16(acc[0][2 * jj],     al0, bh[0], bh[1]);
                mma_bf16(acc[1][2 * jj],     al1, bh[0], bh[1]);
                mma_bf16(acc[0][2 * jj + 1], al0, bh[2], bh[3]);
                mma_bf16(acc[1][2 * jj + 1], al1, bh[2], bh[3]);
            }
        }

        if (pre) {
            char* nstg = tiles + (s ^ 1) * STAGE_BYTES;
#pragma unroll
            for (int j = 0; j < 16; j++) {
                uint32_t hp = __byte_perm(va[j], vb[j], 0x5410);
                uint32_t lp = __byte_perm(va[j], vb[j], 0x7632);
                uint32_t so = (uint32_t)(rowb + 8 * j) * A_STRIDE + (uint32_t)kp * 4;
                *(uint32_t*)(nstg + so) = hp;
                *(uint32_t*)(nstg + 18432 + so) = lp;
            }
            cp_wait0();
        }
        __syncthreads();
    }

    // ---- epilogue: bias add, write raw p into u layout ----
    int row0 = warp_m * 32 + (lane >> 2);
#pragma unroll
    for (int m = 0; m < 2; m++) {
        int r_a = row0 + m * 16;
        int n_a = n0 + r_a, n_b = n_a + 8;
        int ba = n_a / 36, pa = n_a - ba * 36;
        int bb = n_b / 36, pbs = n_b - bb * 36;
        size_t ua = (size_t)ba * 9216 + (size_t)pa * 8;   // + r-part*8 added via co
        size_t ub = (size_t)bb * 9216 + (size_t)pbs * 8;
#pragma unroll
        for (int nf = 0; nf < 8; nf++) {
            int col = warp_n * 64 + nf * 8 + (lane & 3) * 2;
#pragma unroll
            for (int e = 0; e < 2; e++) {
                int lc = col + e;
                int co = co0 + lc;
                float bias = s_bias[lc];
                size_t roff = (size_t)((co & 31) * 36) * 8 + (co >> 5);
                g_u[ua + roff] = acc[m][nf][e] + bias;
                g_u[ub + roff] = acc[m][nf][2 + e] + bias;
            }
        }
    }
}

// ---------------- squash u in place ----------------
__global__ void squash_kernel() {
    int idx = blockIdx.x * 256 + threadIdx.x;
    if (idx >= 512 * 1152) return;
    float4 v0 = *reinterpret_cast<float4*>(&g_u[(size_t)idx * 8]);
    float4 v1 = *reinterpret_cast<float4*>(&g_u[(size_t)idx * 8 + 4]);
    float sn = v0.x * v0.x + v0.y * v0.y + v0.z * v0.z + v0.w * v0.w +
               v1.x * v1.x + v1.y * v1.y + v1.z * v1.z + v1.w * v1.w;
    float sc = sqrtf(sn) / (1.f + sn);
    v0.x *= sc; v0.y *= sc; v0.z *= sc; v0.w *= sc;
    v1.x *= sc; v1.y *= sc; v1.z *= sc; v1.w *= sc;
    *reinterpret_cast<float4*>(&g_u[(size_t)idx * 8]) = v0;
    *reinterpret_cast<float4*>(&g_u[(size_t)idx * 8 + 4]) = v1;
}

// ---------------- priors[b,c,r,o] = sum_i u[b,r,i] * route_w[c,r,i,o] ----------------
// Weights hoisted to registers; u read via __ldg (L1 broadcast); no inner syncs.
__global__ void __launch_bounds__(256) priors_kernel(const float* __restrict__ rw) {
    __shared__ float s_w[2048];
    int tid = threadIdx.x;
    int r0 = blockIdx.x * 16;
    int c = blockIdx.y;
    const float* wsrc = rw + (size_t)c * 147456 + (size_t)r0 * 128;
    for (int i = tid; i < 2048; i += 256) s_w[i] = wsrc[i];
    __syncthreads();
    int rl = tid >> 4, o = tid & 15;
    float wr[8];
#pragma unroll
    for (int i = 0; i < 8; i++) wr[i] = s_w[rl * 128 + i * 16 + o];
    const float4* usrc = (const float4*)(g_u + (size_t)(r0 + rl) * 8);
    float* pdst = g_priors + (size_t)c * 18432 + (size_t)r0 * 16 + tid;
#pragma unroll 4
    for (int b = 0; b < 512; b++) {
        float4 u0 = __ldg(usrc + (size_t)b * 2304);
        float4 u1 = __ldg(usrc + (size_t)b * 2304 + 1);
        float acc = u0.x * wr[0] + u0.y * wr[1] + u0.z * wr[2] + u0.w * wr[3] +
                    u1.x * wr[4] + u1.y * wr[5] + u1.z * wr[6] + u1.w * wr[7];
        pdst[(size_t)b * 184320] = acc;
    }
}

// ---------------- routing: one block per (b,c); 3 iterations in smem ----------------
__device__ __forceinline__ float blk_reduce_max(float v, float* red) {
#pragma unroll
    for (int s = 16; s; s >>= 1) v = fmaxf(v, __shfl_xor_sync(0xffffffffu, v, s));
    if ((threadIdx.x & 31) == 0) red[threadIdx.x >> 5] = v;
    __syncthreads();
    float r = red[0];
#pragma unroll
    for (int i = 1; i < 8; i++) r = fmaxf(r, red[i]);
    __syncthreads();
    return r;
}
__device__ __forceinline__ float blk_reduce_sum(float v, float* red) {
#pragma unroll
    for (int s = 16; s; s >>= 1) v += __shfl_xor_sync(0xffffffffu, v, s);
    if ((threadIdx.x & 31) == 0) red[threadIdx.x >> 5] = v;
    __syncthreads();
    float r = red[0];
#pragma unroll
    for (int i = 1; i < 8; i++) r += red[i];
    __syncthreads();
    return r;
}

__global__ void __launch_bounds__(256) routing_kernel() {
    extern __shared__ float sm[];
    float* P     = sm;
    float* blog  = sm + 19584;
    float* probs = sm + 20736;
    float* sred  = sm + 21888;
    float* s_s   = sm + 22144;
    float* s_v   = sm + 22160;
    float* red   = sm + 22176;

    int tid = threadIdx.x;
    int b = blockIdx.x, c = blockIdx.y;
    const float* gp = g_priors + ((size_t)b * 10 + c) * 18432;
    for (int idx = tid; idx < 18432; idx += 256) {
        int r = idx >> 4, o = idx & 15;
        P[r * 17 + o] = gp[idx];
    }
    for (int r = tid; r < 1152; r += 256) blog[r] = 0.f;
    __syncthreads();

    int o = tid & 15, rg = tid >> 4;
    for (int it = 0; it < 3; it++) {
        float mx = -1e30f;
        for (int r = tid; r < 1152; r += 256) mx = fmaxf(mx, blog[r]);
        mx = blk_reduce_max(mx, red);
        float se = 0.f;
        for (int r = tid; r < 1152; r += 256) {
            float e = expf(blog[r] - mx);
            probs[r] = e;
            se += e;
        }
        se = blk_reduce_sum(se, red);
        float inv = 1.f / se;

        float acc = 0.f;
        for (int r = rg; r < 1152; r += 16) acc = fmaf(probs[r], P[r * 17 + o], acc);
        sred[tid] = acc;
        __syncthreads();
        if (tid < 16) {
            float s = 0.f;
#pragma unroll
            for (int g = 0; g < 16; g++) s += sred[g * 16 + tid];
            s_s[tid] = s * inv;
        }
        __syncthreads();
        if (tid < 16) {
            float sn = 0.f;
#pragma unroll
            for (int oo = 0; oo < 16; oo++) sn += s_s[oo] * s_s[oo];
            float sc = sqrtf(sn) / (1.f + sn);
            s_v[tid] = s_s[tid] * sc;
            if (tid == 0 && it == 2) g_logits[b * 10 + c] = sn / (1.f + sn);
        }
        __syncthreads();
        if (it < 2) {
            for (int r = tid; r < 1152; r += 256) {
                float a = 0.f;
#pragma unroll
                for (int oo = 0; oo < 16; oo++) a = fmaf(P[r * 17 + oo], s_v[oo], a);
                blog[r] += a;
            }
            __syncthreads();
        }
    }
}

// ---------------- final softmax over 10 classes ----------------
__global__ void final_kernel(float* __restrict__ out) {
    int b = blockIdx.x * blockDim.x + threadIdx.x;
    if (b >= 512) return;
    float l[10];
    float mx = -1e30f;
#pragma unroll
    for (int i = 0; i < 10; i++) { l[i] = g_logits[b * 10 + i]; mx = fmaxf(mx, l[i]); }
    float se = 0.f;
#pragma unroll
    for (int i = 0; i < 10; i++) { l[i] = expf(l[i] - mx); se += l[i]; }
    float inv = 1.f / se;
#pragma unroll
    for (int i = 0; i < 10; i++) out[b * 10 + i] = l[i] * inv;
}

// ---------------- launch ----------------
extern "C" void kernel_launch(void* const* d_in, const int* in_sizes, int n_in,
                              void* d_out, int out_size) {
    const float* x       = (const float*)d_in[0];
    const float* conv_w  = (const float*)d_in[1];
    const float* conv_b  = (const float*)d_in[2];
    const float* prim_w  = (const float*)d_in[3];
    const float* prim_b  = (const float*)d_in[4];
    const float* route_w = (const float*)d_in[5];
    float* out = (float*)d_out;

    conv1_kernel<<<512, 256>>>(x, conv_w, conv_b);
    wsplit_kernel<<<20736, 256>>>(prim_w);
    cudaFuncSetAttribute(conv2_mma_kernel, cudaFuncAttributeMaxDynamicSharedMemorySize, 148992);
    conv2_mma_kernel<<<dim3(144, 2), 256, 148992>>>(prim_b);
    squash_kernel<<<2304, 256>>>();
    priors_kernel<<<dim3(72, 10), 256>>>(route_w);
    cudaFuncSetAttribute(routing_kernel, cudaFuncAttributeMaxDynamicSharedMemorySize, 90112);
    routing_kernel<<<dim3(512, 10), 256, 22184 * 4>>>();
    final_kernel<<<2, 256>>>(out);
}

// round 14
// speedup vs baseline: 7.9278x; 1.7277x over previous
#include <cuda_runtime.h>
#include <cuda_bf16.h>
#include <cuda_fp16.h>
#include <math.h>
#include <stdint.h>

// ---------------- scratch (device globals: allocation-free) ----------------
static __device__ __half g_yh[52428800];             // conv1 out fp16: (512,256,20,20) 104.9 MB
static __device__ __half g_wf[5308416];              // prim_w fp16: [256][20736]
static __device__ int g_koff[20736];                 // k -> ci*400 + kh*20 + kw
static __device__ float g_u[4718592];                // u: (512,1152,8)
static __device__ __half g_priors[94371840];         // priors fp16: (512,10,1152,16) 188 MB
static __device__ float g_logits[5120];              // (512,10)

// ---------------- helpers ----------------
__device__ __forceinline__ uint32_t smem_u32(const void* p) {
    uint32_t a;
    asm("{ .reg .u64 t; cvta.to.shared.u64 t, %1; cvt.u32.u64 %0, t; }" : "=r"(a) : "l"(p));
    return a;
}
__device__ __forceinline__ void ldsm4(uint32_t* r, uint32_t addr) {
    asm volatile("ldmatrix.sync.aligned.m8n8.x4.shared.b16 {%0,%1,%2,%3}, [%4];"
                 : "=r"(r[0]), "=r"(r[1]), "=r"(r[2]), "=r"(r[3]) : "r"(addr));
}
__device__ __forceinline__ void mma_f16(float* c, const uint32_t* a, uint32_t b0, uint32_t b1) {
    asm volatile("mma.sync.aligned.m16n8k16.row.col.f32.f16.f16.f32 "
                 "{%0,%1,%2,%3}, {%4,%5,%6,%7}, {%8,%9}, {%0,%1,%2,%3};"
                 : "+f"(c[0]), "+f"(c[1]), "+f"(c[2]), "+f"(c[3])
                 : "r"(a[0]), "r"(a[1]), "r"(a[2]), "r"(a[3]), "r"(b0), "r"(b1));
}
__device__ __forceinline__ void cp_async16(uint32_t saddr, const void* gaddr) {
    asm volatile("cp.async.cg.shared.global [%0], [%1], 16;" :: "r"(saddr), "l"(gaddr));
}
__device__ __forceinline__ void cp_commit() { asm volatile("cp.async.commit_group;"); }
__device__ __forceinline__ void cp_wait0() { asm volatile("cp.async.wait_group 0;" ::: "memory"); }
// packed dual-fp32 FMA (Blackwell base ISA, sm_100+)
__device__ __forceinline__ unsigned long long fma2(unsigned long long a, unsigned long long b,
                                                   unsigned long long c) {
    unsigned long long d;
    asm("fma.rn.f32x2 %0, %1, %2, %3;" : "=l"(d) : "l"(a), "l"(b), "l"(c));
    return d;
}
__device__ __forceinline__ unsigned long long bcast2(float v) {
    unsigned long long d;
    asm("mov.b64 %0, {%1, %1};" : "=l"(d) : "f"(v));
    return d;
}

// ---------------- conv1: x(512,1,28,28) * w(256,1,9,9) -> g_yh fp16 ----------------
// f32x2 packed math: acc pair A=(a0,a1), B=(a2,a3); image in two smem copies
// (s0 aligned, s1 shifted by one float) so every (ip[k],ip[k+1]) pair is an
// 8B-aligned LDS.64 broadcast.
__global__ void __launch_bounds__(256) conv1_kernel(const float* __restrict__ x,
                                                    const float* __restrict__ w,
                                                    const float* __restrict__ cb) {
    __shared__ float s0[784];
    __shared__ float s1[784];
    int b = blockIdx.x;
    int co = threadIdx.x;
    for (int i = threadIdx.x; i < 784; i += 256) {
        float v = x[b * 784 + i];
        s0[i] = v;
        if (i > 0) s1[i - 1] = v;
    }
    float wreg[81];
#pragma unroll
    for (int j = 0; j < 81; j++) wreg[j] = w[co * 81 + j];
    float bs = cb[co];
    __syncthreads();
    __half* outp = g_yh + ((size_t)b * 256 + co) * 400;
    for (int oh = 0; oh < 20; oh++) {
        for (int owg = 0; owg < 20; owg += 4) {
            unsigned long long A = bcast2(bs), B = A;
#pragma unroll
            for (int kh = 0; kh < 9; kh++) {
                int base = (oh + kh) * 28 + owg;   // even
#pragma unroll
                for (int kw = 0; kw < 9; kw++) {
                    int idx = base + kw;
                    unsigned long long pA, pB;
                    if ((kw & 1) == 0) {
                        pA = *(const unsigned long long*)&s0[idx];
                        pB = *(const unsigned long long*)&s0[idx + 2];
                    } else {
                        pA = *(const unsigned long long*)&s1[idx - 1];
                        pB = *(const unsigned long long*)&s1[idx + 1];
                    }
                    unsigned long long W = bcast2(wreg[kh * 9 + kw]);
                    A = fma2(pA, W, A);
                    B = fma2(pB, W, B);
                }
            }
            float2 fA = *(float2*)&A, fB = *(float2*)&B;
            __half2 h0 = __floats2half2_rn(fA.x, fA.y);
            __half2 h1 = __floats2half2_rn(fB.x, fB.y);
            uint2 pk = make_uint2(*(uint32_t*)&h0, *(uint32_t*)&h1);
            *reinterpret_cast<uint2*>(outp + oh * 20 + owg) = pk;
        }
    }
}

// ---------------- convert prim_w to fp16 + build koff table ----------------
__global__ void wconv_kernel(const float* __restrict__ w) {
    int i = blockIdx.x * 256 + threadIdx.x;
    if (i < 5308416) g_wf[i] = __float2half(w[i]);
    if (i < 20736) {
        int ci = i / 81, rr = i - ci * 81, kh = rr / 9, kw = rr - kh * 9;
        g_koff[i] = ci * 400 + kh * 20 + kw;
    }
}

// ---------------- conv2 via warp-MMA fp16 implicit GEMM (single pass) ----------------
// C[n(18432), co(256)] = sum_k Patch[n,k] * W[co,k]
// CTA tile 128(n) x 128(co), BK=64. 8 warps (4m x 2n), warp tile 32x64.
// smem per stage: A 128x144B + B 128x144B = 36864B; 2 stages -> 2 CTAs/SM.
#define A_STRIDE 144
#define STAGE_BYTES 36864
__global__ void __launch_bounds__(256, 2) conv2_mma_kernel(const float* __restrict__ pb) {
    extern __shared__ char smc[];
    int* s_nbase = (int*)smc;                 // [128]
    float* s_bias = (float*)(smc + 512);      // [128]
    char* tiles = smc + 1536;
    uint32_t sTiles = smem_u32(tiles);

    int tid = threadIdx.x, lane = tid & 31, wid = tid >> 5;
    int n0 = blockIdx.x * 128;
    int co0 = blockIdx.y * 128;

    if (tid < 128) {
        int n = n0 + tid;
        int b = n / 36, pos = n - b * 36;
        int oh = pos / 6, ow = pos - oh * 6;
        s_nbase[tid] = b * 102400 + oh * 40 + ow * 2;
        s_bias[tid] = pb[co0 + tid];
    }
    __syncthreads();

    // producer mappings
    int kp = tid & 31;        // A: covers k=2kp,2kp+1
    int rowb = tid >> 5;      // A rows rowb+8j
    int bchunk = tid & 7;     // B 16B chunk
    int brow0 = tid >> 3;     // B rows brow0+32rr

    int warp_m = wid >> 1, warp_n = wid & 1;
    uint32_t a_off = (uint32_t)(warp_m * 32 + (lane & 7) + ((lane >> 3) & 1) * 8) * A_STRIDE
                     + (uint32_t)(lane >> 4) * 16;
    uint32_t b_off = 18432u + (uint32_t)(warp_n * 64 + (lane & 7) + ((lane >> 4) & 1) * 8) * A_STRIDE
                     + (uint32_t)((lane >> 3) & 1) * 16;

    float acc[2][8][4];
#pragma unroll
    for (int m = 0; m < 2; m++)
#pragma unroll
        for (int nf = 0; nf < 8; nf++)
#pragma unroll
            for (int e = 0; e < 4; e++) acc[m][nf][e] = 0.f;

    const unsigned short* yu = (const unsigned short*)g_yh;
    unsigned short va[16], vb[16];

    // prologue: stage 0
    {
#pragma unroll
        for (int rr = 0; rr < 4; rr++) {
            int row = brow0 + rr * 32;
            size_t g = (size_t)(co0 + row) * 41472 + (size_t)bchunk * 16;
            uint32_t so = 18432u + (uint32_t)row * A_STRIDE + (uint32_t)bchunk * 16;
            cp_async16(sTiles + so, (const char*)g_wf + g);
        }
        cp_commit();
        int koff0 = g_koff[2 * kp];
        int koff1 = g_koff[2 * kp + 1];
#pragma unroll
        for (int j = 0; j < 16; j++) {
            int nb = s_nbase[rowb + 8 * j];
            va[j] = yu[nb + koff0];
            vb[j] = yu[nb + koff1];
        }
#pragma unroll
        for (int j = 0; j < 16; j++) {
            uint32_t pk = (uint32_t)va[j] | ((uint32_t)vb[j] << 16);
            uint32_t so = (uint32_t)(rowb + 8 * j) * A_STRIDE + (uint32_t)kp * 4;
            *(uint32_t*)(tiles + so) = pk;
        }
        cp_wait0();
        __syncthreads();
    }

    for (int c = 0; c < 324; c++) {
        int s = c & 1;
        uint32_t stage = sTiles + (uint32_t)s * STAGE_BYTES;
        bool pre = (c + 1) < 324;

        if (pre) {
            int k0n = (c + 1) * 64;
            uint32_t nstage = sTiles + (uint32_t)(s ^ 1) * STAGE_BYTES;
#pragma unroll
            for (int rr = 0; rr < 4; rr++) {
                int row = brow0 + rr * 32;
                size_t g = (size_t)(co0 + row) * 41472 + (size_t)k0n * 2 + (size_t)bchunk * 16;
                uint32_t so = 18432u + (uint32_t)row * A_STRIDE + (uint32_t)bchunk * 16;
                cp_async16(nstage + so, (const char*)g_wf + g);
            }
            cp_commit();
            int koff0 = g_koff[k0n + 2 * kp];
            int koff1 = g_koff[k0n + 2 * kp + 1];
#pragma unroll
            for (int j = 0; j < 16; j++) {
                int nb = s_nbase[rowb + 8 * j];
                va[j] = yu[nb + koff0];
                vb[j] = yu[nb + koff1];
            }
        }

        // compute current stage
#pragma unroll
        for (int ks = 0; ks < 4; ks++) {
            uint32_t ko = (uint32_t)ks * 32;
            uint32_t a0[4], a1[4];
            ldsm4(a0, stage + a_off + ko);
            ldsm4(a1, stage + a_off + 16 * A_STRIDE + ko);
#pragma unroll
            for (int jj = 0; jj < 4; jj++) {
                uint32_t bb[4];
                ldsm4(bb, stage + b_off + (uint32_t)jj * (16 * A_STRIDE) + ko);
                mma_f16(acc[0][2 * jj],     a0, bb[0], bb[1]);
                mma_f16(acc[1][2 * jj],     a1, bb[0], bb[1]);
                mma_f16(acc[0][2 * jj + 1], a0, bb[2], bb[3]);
                mma_f16(acc[1][2 * jj + 1], a1, bb[2], bb[3]);
            }
        }

        if (pre) {
            char* nstg = tiles + (s ^ 1) * STAGE_BYTES;
#pragma unroll
            for (int j = 0; j < 16; j++) {
                uint32_t pk = (uint32_t)va[j] | ((uint32_t)vb[j] << 16);
                uint32_t so = (uint32_t)(rowb + 8 * j) * A_STRIDE + (uint32_t)kp * 4;
                *(uint32_t*)(nstg + so) = pk;
            }
            cp_wait0();
        }
        __syncthreads();
    }

    // epilogue: bias add, write raw p into u layout
    int row0 = warp_m * 32 + (lane >> 2);
#pragma unroll
    for (int m = 0; m < 2; m++) {
        int r_a = row0 + m * 16;
        int n_a = n0 + r_a, n_b = n_a + 8;
        int ba = n_a / 36, pa = n_a - ba * 36;
        int bb2 = n_b / 36, pbs = n_b - bb2 * 36;
        size_t ua = (size_t)ba * 9216 + (size_t)pa * 8;
        size_t ub = (size_t)bb2 * 9216 + (size_t)pbs * 8;
#pragma unroll
        for (int nf = 0; nf < 8; nf++) {
            int col = warp_n * 64 + nf * 8 + (lane & 3) * 2;
#pragma unroll
            for (int e = 0; e < 2; e++) {
                int lc = col + e;
                int co = co0 + lc;
                float bias = s_bias[lc];
                size_t roff = (size_t)((co & 31) * 36) * 8 + (co >> 5);
                g_u[ua + roff] = acc[m][nf][e] + bias;
                g_u[ub + roff] = acc[m][nf][2 + e] + bias;
            }
        }
    }
}

// ---------------- squash u in place ----------------
__global__ void squash_kernel() {
    int idx = blockIdx.x * 256 + threadIdx.x;
    if (idx >= 512 * 1152) return;
    float4 v0 = *reinterpret_cast<float4*>(&g_u[(size_t)idx * 8]);
    float4 v1 = *reinterpret_cast<float4*>(&g_u[(size_t)idx * 8 + 4]);
    float sn = v0.x * v0.x + v0.y * v0.y + v0.z * v0.z + v0.w * v0.w +
               v1.x * v1.x + v1.y * v1.y + v1.z * v1.z + v1.w * v1.w;
    float sc = sqrtf(sn) / (1.f + sn);
    v0.x *= sc; v0.y *= sc; v0.z *= sc; v0.w *= sc;
    v1.x *= sc; v1.y *= sc; v1.z *= sc; v1.w *= sc;
    *reinterpret_cast<float4*>(&g_u[(size_t)idx * 8]) = v0;
    *reinterpret_cast<float4*>(&g_u[(size_t)idx * 8 + 4]) = v1;
}

// ---------------- priors[b,c,r,o] = sum_i u[b,r,i] * route_w[c,r,i,o]  (fp16 out) ----------------
__global__ void __launch_bounds__(256) priors_kernel(const float* __restrict__ rw) {
    __shared__ float s_w[2048];
    int tid = threadIdx.x;
    int r0 = blockIdx.x * 16;
    int c = blockIdx.y;
    const float* wsrc = rw + (size_t)c * 147456 + (size_t)r0 * 128;
    for (int i = tid; i < 2048; i += 256) s_w[i] = wsrc[i];
    __syncthreads();
    int rl = tid >> 4, o = tid & 15;
    float wr[8];
#pragma unroll
    for (int i = 0; i < 8; i++) wr[i] = s_w[rl * 128 + i * 16 + o];
    const float4* usrc = (const float4*)(g_u + (size_t)(r0 + rl) * 8);
    __half* pdst = g_priors + (size_t)c * 18432 + (size_t)r0 * 16 + tid;
#pragma unroll 4
    for (int b = 0; b < 512; b++) {
        float4 u0 = __ldg(usrc + (size_t)b * 2304);
        float4 u1 = __ldg(usrc + (size_t)b * 2304 + 1);
        float acc = u0.x * wr[0] + u0.y * wr[1] + u0.z * wr[2] + u0.w * wr[3] +
                    u1.x * wr[4] + u1.y * wr[5] + u1.z * wr[6] + u1.w * wr[7];
        pdst[(size_t)b * 184320] = __float2half(acc);
    }
}

// ---------------- routing: one block per (b,c); 3 iterations in smem ----------------
__device__ __forceinline__ float blk_reduce_max(float v, float* red) {
#pragma unroll
    for (int s = 16; s; s >>= 1) v = fmaxf(v, __shfl_xor_sync(0xffffffffu, v, s));
    if ((threadIdx.x & 31) == 0) red[threadIdx.x >> 5] = v;
    __syncthreads();
    float r = red[0];
#pragma unroll
    for (int i = 1; i < 8; i++) r = fmaxf(r, red[i]);
    __syncthreads();
    return r;
}
__device__ __forceinline__ float blk_reduce_sum(float v, float* red) {
#pragma unroll
    for (int s = 16; s; s >>= 1) v += __shfl_xor_sync(0xffffffffu, v, s);
    if ((threadIdx.x & 31) == 0) red[threadIdx.x >> 5] = v;
    __syncthreads();
    float r = red[0];
#pragma unroll
    for (int i = 1; i < 8; i++) r += red[i];
    __syncthreads();
    return r;
}

__global__ void __launch_bounds__(256) routing_kernel() {
    extern __shared__ float sm[];
    float* P     = sm;          // [1152][17]
    float* blog  = sm + 19584;
    float* probs = sm + 20736;
    float* sred  = sm + 21888;
    float* s_s   = sm + 22144;
    float* s_v   = sm + 22160;
    float* red   = sm + 22176;

    int tid = threadIdx.x;
    int b = blockIdx.x, c = blockIdx.y;
    const uint4* gp = (const uint4*)(g_priors + ((size_t)b * 10 + c) * 18432);
    for (int i = tid; i < 2304; i += 256) {      // 8 halfs per iter
        uint4 v = __ldg(gp + i);
        int r = i >> 1, o0 = (i & 1) * 8;
        float* dst = &P[r * 17 + o0];
        __half2 h;
        h = *(__half2*)&v.x; float2 f0 = __half22float2(h);
        h = *(__half2*)&v.y; float2 f1 = __half22float2(h);
        h = *(__half2*)&v.z; float2 f2 = __half22float2(h);
        h = *(__half2*)&v.w; float2 f3 = __half22float2(h);
        dst[0] = f0.x; dst[1] = f0.y; dst[2] = f1.x; dst[3] = f1.y;
        dst[4] = f2.x; dst[5] = f2.y; dst[6] = f3.x; dst[7] = f3.y;
    }
    for (int r = tid; r < 1152; r += 256) blog[r] = 0.f;
    __syncthreads();

    int o = tid & 15, rg = tid >> 4;
    for (int it = 0; it < 3; it++) {
        float mx = -1e30f;
        for (int r = tid; r < 1152; r += 256) mx = fmaxf(mx, blog[r]);
        mx = blk_reduce_max(mx, red);
        float se = 0.f;
        for (int r = tid; r < 1152; r += 256) {
            float e = expf(blog[r] - mx);
            probs[r] = e;
            se += e;
        }
        se = blk_reduce_sum(se, red);
        float inv = 1.f / se;

        float acc = 0.f;
        for (int r = rg; r < 1152; r += 16) acc = fmaf(probs[r], P[r * 17 + o], acc);
        sred[tid] = acc;
        __syncthreads();
        if (tid < 16) {
            float s = 0.f;
#pragma unroll
            for (int g = 0; g < 16; g++) s += sred[g * 16 + tid];
            s_s[tid] = s * inv;
        }
        __syncthreads();
        if (tid < 16) {
            float sn = 0.f;
#pragma unroll
            for (int oo = 0; oo < 16; oo++) sn += s_s[oo] * s_s[oo];
            float sc = sqrtf(sn) / (1.f + sn);
            s_v[tid] = s_s[tid] * sc;
            if (tid == 0 && it == 2) g_logits[b * 10 + c] = sn / (1.f + sn);
        }
        __syncthreads();
        if (it < 2) {
            for (int r = tid; r < 1152; r += 256) {
                float a = 0.f;
#pragma unroll
                for (int oo = 0; oo < 16; oo++) a = fmaf(P[r * 17 + oo], s_v[oo], a);
                blog[r] += a;
            }
            __syncthreads();
        }
    }
}

// ---------------- final softmax over 10 classes ----------------
__global__ void final_kernel(float* __restrict__ out) {
    int b = blockIdx.x * blockDim.x + threadIdx.x;
    if (b >= 512) return;
    float l[10];
    float mx = -1e30f;
#pragma unroll
    for (int i = 0; i < 10; i++) { l[i] = g_logits[b * 10 + i]; mx = fmaxf(mx, l[i]); }
    float se = 0.f;
#pragma unroll
    for (int i = 0; i < 10; i++) { l[i] = expf(l[i] - mx); se += l[i]; }
    float inv = 1.f / se;
#pragma unroll
    for (int i = 0; i < 10; i++) out[b * 10 + i] = l[i] * inv;
}

// ---------------- launch ----------------
extern "C" void kernel_launch(void* const* d_in, const int* in_sizes, int n_in,
                              void* d_out, int out_size) {
    const float* x       = (const float*)d_in[0];
    const float* conv_w  = (const float*)d_in[1];
    const float* conv_b  = (const float*)d_in[2];
    const float* prim_w  = (const float*)d_in[3];
    const float* prim_b  = (const float*)d_in[4];
    const float* route_w = (const float*)d_in[5];
    float* out = (float*)d_out;

    conv1_kernel<<<512, 256>>>(x, conv_w, conv_b);
    wconv_kernel<<<20736, 256>>>(prim_w);
    cudaFuncSetAttribute(conv2_mma_kernel, cudaFuncAttributeMaxDynamicSharedMemorySize, 75264);
    conv2_mma_kernel<<<dim3(144, 2), 256, 75264>>>(prim_b);
    squash_kernel<<<2304, 256>>>();
    priors_kernel<<<dim3(72, 10), 256>>>(route_w);
    cudaFuncSetAttribute(routing_kernel, cudaFuncAttributeMaxDynamicSharedMemorySize, 90112);
    routing_kernel<<<dim3(512, 10), 256, 22184 * 4>>>();
    final_kernel<<<2, 256>>>(out);
}

// round 15
// speedup vs baseline: 11.3204x; 1.4279x over previous
#include <cuda_runtime.h>
#include <cuda_bf16.h>
#include <cuda_fp16.h>
#include <math.h>
#include <stdint.h>

// ---------------- scratch (device globals: allocation-free) ----------------
static __device__ __half g_yh[52428800];             // conv1 out fp16 CHANNEL-LAST: (512,20,20,256)
static __device__ __half g_wf[5308416];              // prim_w fp16 reordered: [256][(kh*9+kw)*256+ci]
static __device__ float g_u[4718592];                // u: (512,1152,8)
static __device__ __half g_priors[94371840];         // priors fp16: (512,10,1152,16)
static __device__ float g_logits[5120];              // (512,10)

// ---------------- helpers ----------------
__device__ __forceinline__ uint32_t smem_u32(const void* p) {
    uint32_t a;
    asm("{ .reg .u64 t; cvta.to.shared.u64 t, %1; cvt.u32.u64 %0, t; }" : "=r"(a) : "l"(p));
    return a;
}
__device__ __forceinline__ void ldsm4(uint32_t* r, uint32_t addr) {
    asm volatile("ldmatrix.sync.aligned.m8n8.x4.shared.b16 {%0,%1,%2,%3}, [%4];"
                 : "=r"(r[0]), "=r"(r[1]), "=r"(r[2]), "=r"(r[3]) : "r"(addr));
}
__device__ __forceinline__ void mma_f16(float* c, const uint32_t* a, uint32_t b0, uint32_t b1) {
    asm volatile("mma.sync.aligned.m16n8k16.row.col.f32.f16.f16.f32 "
                 "{%0,%1,%2,%3}, {%4,%5,%6,%7}, {%8,%9}, {%0,%1,%2,%3};"
                 : "+f"(c[0]), "+f"(c[1]), "+f"(c[2]), "+f"(c[3])
                 : "r"(a[0]), "r"(a[1]), "r"(a[2]), "r"(a[3]), "r"(b0), "r"(b1));
}
__device__ __forceinline__ void cp_async16(uint32_t saddr, const void* gaddr) {
    asm volatile("cp.async.cg.shared.global [%0], [%1], 16;" :: "r"(saddr), "l"(gaddr));
}
__device__ __forceinline__ void cp_commit() { asm volatile("cp.async.commit_group;"); }
__device__ __forceinline__ void cp_wait0() { asm volatile("cp.async.wait_group 0;" ::: "memory"); }
__device__ __forceinline__ void cp_wait1() { asm volatile("cp.async.wait_group 1;" ::: "memory"); }
// packed dual-fp32 FMA (Blackwell base ISA)
__device__ __forceinline__ unsigned long long fma2(unsigned long long a, unsigned long long b,
                                                   unsigned long long c) {
    unsigned long long d;
    asm("fma.rn.f32x2 %0, %1, %2, %3;" : "=l"(d) : "l"(a), "l"(b), "l"(c));
    return d;
}
__device__ __forceinline__ unsigned long long bcast2(float v) {
    unsigned long long d;
    asm("mov.b64 %0, {%1, %1};" : "=l"(d) : "f"(v));
    return d;
}

// ---------------- conv1: x(512,1,28,28) * w(256,1,9,9) -> g_yh channel-last fp16 ----------------
__global__ void __launch_bounds__(256) conv1_kernel(const float* __restrict__ x,
                                                    const float* __restrict__ w,
                                                    const float* __restrict__ cb) {
    __shared__ float s0[784];
    __shared__ float s1[784];
    int b = blockIdx.x;
    int co = threadIdx.x;
    for (int i = threadIdx.x; i < 784; i += 256) {
        float v = x[b * 784 + i];
        s0[i] = v;
        if (i > 0) s1[i - 1] = v;
    }
    float wreg[81];
#pragma unroll
    for (int j = 0; j < 81; j++) wreg[j] = w[co * 81 + j];
    float bs = cb[co];
    __syncthreads();
    __half* outb = g_yh + (size_t)b * 102400 + co;   // 400*256 per image
    for (int oh = 0; oh < 20; oh++) {
        for (int owg = 0; owg < 20; owg += 4) {
            unsigned long long A = bcast2(bs), B = A;
#pragma unroll
            for (int kh = 0; kh < 9; kh++) {
                int base = (oh + kh) * 28 + owg;   // even
#pragma unroll
                for (int kw = 0; kw < 9; kw++) {
                    int idx = base + kw;
                    unsigned long long pA, pB;
                    if ((kw & 1) == 0) {
                        pA = *(const unsigned long long*)&s0[idx];
                        pB = *(const unsigned long long*)&s0[idx + 2];
                    } else {
                        pA = *(const unsigned long long*)&s1[idx - 1];
                        pB = *(const unsigned long long*)&s1[idx + 1];
                    }
                    unsigned long long W = bcast2(wreg[kh * 9 + kw]);
                    A = fma2(pA, W, A);
                    B = fma2(pB, W, B);
                }
            }
            float2 fA = *(float2*)&A, fB = *(float2*)&B;
            int base = (oh * 20 + owg) * 256;
            outb[base]       = __float2half(fA.x);
            outb[base + 256] = __float2half(fA.y);
            outb[base + 512] = __float2half(fB.x);
            outb[base + 768] = __float2half(fB.y);
        }
    }
}

// ---------------- prim_w -> fp16, reorder k: (ci,kh,kw) -> (kh*9+kw)*256+ci ----------------
__global__ void __launch_bounds__(256) wconv_kernel(const float* __restrict__ w) {
    __shared__ __half sw[81 * 258];
    int co = blockIdx.x, tid = threadIdx.x;
    const float* src = w + (size_t)co * 20736;
    for (int i = tid; i < 20736; i += 256) {
        int ci = i / 81, rr = i - ci * 81;
        sw[rr * 258 + ci] = __float2half(src[i]);
    }
    __syncthreads();
    __half* dst = g_wf + (size_t)co * 20736;
    for (int t = tid; t < 20736; t += 256) {
        int rr = t >> 8, ci = t & 255;
        dst[t] = sw[rr * 258 + ci];
    }
}

// ---------------- conv2 via warp-MMA fp16 implicit GEMM, all-cp.async producers ----------------
// C[n(18432), co(256)] = sum_k Patch[n,k] * W[co,k], k' = (kh,kw,ci)
// CTA tile 128(n) x 128(co), BK=64, 324 iters. 8 warps (4m x 2n), warp tile 32x64.
// Stage: A rows 0-127, B rows 128-255, 144B stride -> 36864 B; 2 stages, 2 CTAs/SM.
#define A_STRIDE 144
#define STAGE_BYTES 36864
__global__ void __launch_bounds__(256, 2) conv2_mma_kernel(const float* __restrict__ pb) {
    extern __shared__ char smc[];
    int* s_nbase = (int*)smc;                 // [128]
    float* s_bias = (float*)(smc + 512);      // [128]
    int* s_koff = (int*)(smc + 1024);         // [324]
    char* tiles = smc + 2368;
    uint32_t sT = smem_u32(tiles);

    int tid = threadIdx.x, lane = tid & 31, wid = tid >> 5;
    int co0 = blockIdx.x * 128;
    int n0 = blockIdx.y * 128;

    if (tid < 128) {
        int n = n0 + tid;
        int b = n / 36, pos = n - b * 36;
        int oh = pos / 6, ow = pos - oh * 6;
        s_nbase[tid] = ((b * 20 + 2 * oh) * 20 + 2 * ow) * 256;
        s_bias[tid] = pb[co0 + tid];
    }
    for (int c = tid; c < 324; c += 256) {
        int khw = c >> 2;
        int kh = khw / 9, kw = khw - 9 * kh;
        s_koff[c] = (kh * 20 + kw) * 256 + (c & 3) * 64;
    }
    __syncthreads();

    int j = tid & 7;        // 16B chunk
    int rowq = tid >> 3;    // 0..31

    int warp_m = wid >> 1, warp_n = wid & 1;
    uint32_t a_off = (uint32_t)(warp_m * 32 + (lane & 7) + ((lane >> 3) & 1) * 8) * A_STRIDE
                     + (uint32_t)(lane >> 4) * 16;
    uint32_t b_off = 128u * A_STRIDE + (uint32_t)(warp_n * 64 + (lane & 7) + ((lane >> 4) & 1) * 8) * A_STRIDE
                     + (uint32_t)((lane >> 3) & 1) * 16;

    float acc[2][8][4];
#pragma unroll
    for (int m = 0; m < 2; m++)
#pragma unroll
        for (int nf = 0; nf < 8; nf++)
#pragma unroll
            for (int e = 0; e < 4; e++) acc[m][nf][e] = 0.f;

    // producer: 8 cp.async of 16B per thread per chunk
#define PRODUCE(sidx, cidx)                                                            \
    do {                                                                               \
        uint32_t st_ = sT + (uint32_t)(sidx) * STAGE_BYTES;                            \
        int koff_ = s_koff[(cidx)];                                                    \
        int k0_ = (cidx) * 64;                                                         \
        _Pragma("unroll")                                                              \
        for (int rr = 0; rr < 4; rr++) {                                               \
            int row = rowq + rr * 32;                                                  \
            const __half* ga = g_yh + s_nbase[row] + koff_ + j * 8;                    \
            cp_async16(st_ + (uint32_t)row * A_STRIDE + (uint32_t)j * 16, ga);         \
            const __half* gb = g_wf + (size_t)(co0 + row) * 20736 + k0_ + j * 8;       \
            cp_async16(st_ + (uint32_t)(128 + row) * A_STRIDE + (uint32_t)j * 16, gb); \
        }                                                                              \
        cp_commit();                                                                   \
    } while (0)

    PRODUCE(0, 0);

    for (int c = 0; c < 324; c++) {
        int s = c & 1;
        uint32_t stage = sT + (uint32_t)s * STAGE_BYTES;
        bool pre = (c + 1) < 324;
        if (pre) {
            PRODUCE(s ^ 1, c + 1);
            cp_wait1();
        } else {
            cp_wait0();
        }
        __syncthreads();

#pragma unroll
        for (int ks = 0; ks < 4; ks++) {
            uint32_t ko = (uint32_t)ks * 32;
            uint32_t a0[4], a1[4];
            ldsm4(a0, stage + a_off + ko);
            ldsm4(a1, stage + a_off + 16 * A_STRIDE + ko);
#pragma unroll
            for (int jj = 0; jj < 4; jj++) {
                uint32_t bb[4];
                ldsm4(bb, stage + b_off + (uint32_t)jj * (16 * A_STRIDE) + ko);
                mma_f16(acc[0][2 * jj],     a0, bb[0], bb[1]);
                mma_f16(acc[1][2 * jj],     a1, bb[0], bb[1]);
                mma_f16(acc[0][2 * jj + 1], a0, bb[2], bb[3]);
                mma_f16(acc[1][2 * jj + 1], a1, bb[2], bb[3]);
            }
        }
        __syncthreads();
    }

    // epilogue: bias add, write raw p into u layout
    int row0 = warp_m * 32 + (lane >> 2);
#pragma unroll
    for (int m = 0; m < 2; m++) {
        int r_a = row0 + m * 16;
        int n_a = n0 + r_a, n_b = n_a + 8;
        int ba = n_a / 36, pa = n_a - ba * 36;
        int bb2 = n_b / 36, pbs = n_b - bb2 * 36;
        size_t ua = (size_t)ba * 9216 + (size_t)pa * 8;
        size_t ub = (size_t)bb2 * 9216 + (size_t)pbs * 8;
#pragma unroll
        for (int nf = 0; nf < 8; nf++) {
            int col = warp_n * 64 + nf * 8 + (lane & 3) * 2;
#pragma unroll
            for (int e = 0; e < 2; e++) {
                int lc = col + e;
                int co = co0 + lc;
                float bias = s_bias[lc];
                size_t roff = (size_t)((co & 31) * 36) * 8 + (co >> 5);
                g_u[ua + roff] = acc[m][nf][e] + bias;
                g_u[ub + roff] = acc[m][nf][2 + e] + bias;
            }
        }
    }
}

// ---------------- squash u in place ----------------
__global__ void squash_kernel() {
    int idx = blockIdx.x * 256 + threadIdx.x;
    if (idx >= 512 * 1152) return;
    float4 v0 = *reinterpret_cast<float4*>(&g_u[(size_t)idx * 8]);
    float4 v1 = *reinterpret_cast<float4*>(&g_u[(size_t)idx * 8 + 4]);
    float sn = v0.x * v0.x + v0.y * v0.y + v0.z * v0.z + v0.w * v0.w +
               v1.x * v1.x + v1.y * v1.y + v1.z * v1.z + v1.w * v1.w;
    float sc = sqrtf(sn) / (1.f + sn);
    v0.x *= sc; v0.y *= sc; v0.z *= sc; v0.w *= sc;
    v1.x *= sc; v1.y *= sc; v1.z *= sc; v1.w *= sc;
    *reinterpret_cast<float4*>(&g_u[(size_t)idx * 8]) = v0;
    *reinterpret_cast<float4*>(&g_u[(size_t)idx * 8 + 4]) = v1;
}

// ---------------- priors[b,c,r,o] = sum_i u[b,r,i] * route_w[c,r,i,o]  (fp16 out) ----------------
__global__ void __launch_bounds__(256) priors_kernel(const float* __restrict__ rw) {
    __shared__ float s_w[2048];
    int tid = threadIdx.x;
    int r0 = blockIdx.x * 16;
    int c = blockIdx.y;
    const float* wsrc = rw + (size_t)c * 147456 + (size_t)r0 * 128;
    for (int i = tid; i < 2048; i += 256) s_w[i] = wsrc[i];
    __syncthreads();
    int rl = tid >> 4, o = tid & 15;
    float wr[8];
#pragma unroll
    for (int i = 0; i < 8; i++) wr[i] = s_w[rl * 128 + i * 16 + o];
    const float4* usrc = (const float4*)(g_u + (size_t)(r0 + rl) * 8);
    __half* pdst = g_priors + (size_t)c * 18432 + (size_t)r0 * 16 + tid;
#pragma unroll 4
    for (int b = 0; b < 512; b++) {
        float4 u0 = __ldg(usrc + (size_t)b * 2304);
        float4 u1 = __ldg(usrc + (size_t)b * 2304 + 1);
        float acc = u0.x * wr[0] + u0.y * wr[1] + u0.z * wr[2] + u0.w * wr[3] +
                    u1.x * wr[4] + u1.y * wr[5] + u1.z * wr[6] + u1.w * wr[7];
        pdst[(size_t)b * 184320] = __float2half(acc);
    }
}

// ---------------- routing: one block per (b,c); P kept as half2 in smem ----------------
__device__ __forceinline__ float blk_reduce_max(float v, float* red) {
#pragma unroll
    for (int s = 16; s; s >>= 1) v = fmaxf(v, __shfl_xor_sync(0xffffffffu, v, s));
    if ((threadIdx.x & 31) == 0) red[threadIdx.x >> 5] = v;
    __syncthreads();
    float r = red[0];
#pragma unroll
    for (int i = 1; i < 8; i++) r = fmaxf(r, red[i]);
    __syncthreads();
    return r;
}
__device__ __forceinline__ float blk_reduce_sum(float v, float* red) {
#pragma unroll
    for (int s = 16; s; s >>= 1) v += __shfl_xor_sync(0xffffffffu, v, s);
    if ((threadIdx.x & 31) == 0) red[threadIdx.x >> 5] = v;
    __syncthreads();
    float r = red[0];
#pragma unroll
    for (int i = 1; i < 8; i++) r += red[i];
    __syncthreads();
    return r;
}

__global__ void __launch_bounds__(256) routing_kernel() {
    extern __shared__ float sm[];
    uint32_t* P2   = (uint32_t*)sm;            // [1152*9] half2 words (pad stride 9)
    float* blog    = sm + 10368;               // 1152
    float* probs   = sm + 11520;               // 1152
    float2* sred   = (float2*)(sm + 12672);    // 256
    float* s_s     = sm + 13184;               // 16
    float2* v2     = (float2*)(sm + 13200);    // 8
    float* red     = sm + 13216;               // 8  (total 13224 words)

    int tid = threadIdx.x;
    int b = blockIdx.x, c = blockIdx.y;
    const uint4* gp = (const uint4*)(g_priors + ((size_t)b * 10 + c) * 18432);
    for (int i = tid; i < 2304; i += 256) {
        uint4 v = __ldg(gp + i);
        int r = i >> 1, part = (i & 1) * 4;
        uint32_t* dst = &P2[r * 9 + part];
        dst[0] = v.x; dst[1] = v.y; dst[2] = v.z; dst[3] = v.w;
    }
    for (int r = tid; r < 1152; r += 256) blog[r] = 0.f;
    __syncthreads();

    int o2 = tid & 7, rg = tid >> 3;
    for (int it = 0; it < 3; it++) {
        float mx = -1e30f;
        for (int r = tid; r < 1152; r += 256) mx = fmaxf(mx, blog[r]);
        mx = blk_reduce_max(mx, red);
        float se = 0.f;
        for (int r = tid; r < 1152; r += 256) {
            float e = expf(blog[r] - mx);
            probs[r] = e;
            se += e;
        }
        se = blk_reduce_sum(se, red);
        float inv = 1.f / se;

        float2 acc = make_float2(0.f, 0.f);
        for (int r = rg; r < 1152; r += 32) {
            float2 f = __half22float2(*(__half2*)&P2[r * 9 + o2]);
            float p = probs[r];
            acc.x = fmaf(p, f.x, acc.x);
            acc.y = fmaf(p, f.y, acc.y);
        }
        sred[tid] = acc;
        __syncthreads();
        if (tid < 16) {
            int oo2 = tid >> 1, comp = tid & 1;
            float s = 0.f;
#pragma unroll
            for (int g = 0; g < 32; g++) {
                float2 t = sred[g * 8 + oo2];
                s += comp ? t.y : t.x;
            }
            s_s[tid] = s * inv;
        }
        __syncthreads();
        if (tid < 8) {
            float sn = 0.f;
#pragma unroll
            for (int oo = 0; oo < 16; oo++) sn += s_s[oo] * s_s[oo];
            float sc = sqrtf(sn) / (1.f + sn);
            v2[tid] = make_float2(s_s[2 * tid] * sc, s_s[2 * tid + 1] * sc);
            if (tid == 0 && it == 2) g_logits[b * 10 + c] = sn / (1.f + sn);
        }
        __syncthreads();
        if (it < 2) {
            for (int r = tid; r < 1152; r += 256) {
                float a = 0.f;
#pragma unroll
                for (int jj = 0; jj < 8; jj++) {
                    float2 f = __half22float2(*(__half2*)&P2[r * 9 + jj]);
                    float2 vv = v2[jj];
                    a = fmaf(f.x, vv.x, a);
                    a = fmaf(f.y, vv.y, a);
                }
                blog[r] += a;
            }
            __syncthreads();
        }
    }
}

// ---------------- final softmax over 10 classes ----------------
__global__ void final_kernel(float* __restrict__ out) {
    int b = blockIdx.x * blockDim.x + threadIdx.x;
    if (b >= 512) return;
    float l[10];
    float mx = -1e30f;
#pragma unroll
    for (int i = 0; i < 10; i++) { l[i] = g_logits[b * 10 + i]; mx = fmaxf(mx, l[i]); }
    float se = 0.f;
#pragma unroll
    for (int i = 0; i < 10; i++) { l[i] = expf(l[i] - mx); se += l[i]; }
    float inv = 1.f / se;
#pragma unroll
    for (int i = 0; i < 10; i++) out[b * 10 + i] = l[i] * inv;
}

// ---------------- launch ----------------
extern "C" void kernel_launch(void* const* d_in, const int* in_sizes, int n_in,
                              void* d_out, int out_size) {
    const float* x       = (const float*)d_in[0];
    const float* conv_w  = (const float*)d_in[1];
    const float* conv_b  = (const float*)d_in[2];
    const float* prim_w  = (const float*)d_in[3];
    const float* prim_b  = (const float*)d_in[4];
    const float* route_w = (const float*)d_in[5];
    float* out = (float*)d_out;

    conv1_kernel<<<512, 256>>>(x, conv_w, conv_b);
    wconv_kernel<<<256, 256>>>(prim_w);
    cudaFuncSetAttribute(conv2_mma_kernel, cudaFuncAttributeMaxDynamicSharedMemorySize, 76096);
    conv2_mma_kernel<<<dim3(2, 144), 256, 76096>>>(prim_b);
    squash_kernel<<<2304, 256>>>();
    priors_kernel<<<dim3(72, 10), 256>>>(route_w);
    cudaFuncSetAttribute(routing_kernel, cudaFuncAttributeMaxDynamicSharedMemorySize, 52896);
    routing_kernel<<<dim3(512, 10), 256, 52896>>>();
    final_kernel<<<2, 256>>>(out);
}

// round 16
// speedup vs baseline: 13.0781x; 1.1553x over previous
#include <cuda_runtime.h>
#include <cuda_bf16.h>
#include <cuda_fp16.h>
#include <math.h>
#include <stdint.h>

// ---------------- scratch (device globals: allocation-free) ----------------
static __device__ __half g_xh[401408];               // x fp16: (512,28,28)
static __device__ __half g_wc1[24576];               // conv1 w fp16 padded: [256][96]
static __device__ __half g_yh[52428800];             // conv1 out fp16 CHANNEL-LAST: (512,20,20,256)
static __device__ __half g_wf[5308416];              // prim_w fp16 reordered: [256][(kh*9+kw)*256+ci]
static __device__ float g_u[4718592];                // u: (512,1152,8)
static __device__ __half g_priors[94371840];         // priors fp16: (512,10,1152,16)
static __device__ float g_logits[5120];              // (512,10)

// ---------------- helpers ----------------
__device__ __forceinline__ uint32_t smem_u32(const void* p) {
    uint32_t a;
    asm("{ .reg .u64 t; cvta.to.shared.u64 t, %1; cvt.u32.u64 %0, t; }" : "=r"(a) : "l"(p));
    return a;
}
__device__ __forceinline__ void ldsm4(uint32_t* r, uint32_t addr) {
    asm volatile("ldmatrix.sync.aligned.m8n8.x4.shared.b16 {%0,%1,%2,%3}, [%4];"
                 : "=r"(r[0]), "=r"(r[1]), "=r"(r[2]), "=r"(r[3]) : "r"(addr));
}
__device__ __forceinline__ void mma_f16(float* c, const uint32_t* a, uint32_t b0, uint32_t b1) {
    asm volatile("mma.sync.aligned.m16n8k16.row.col.f32.f16.f16.f32 "
                 "{%0,%1,%2,%3}, {%4,%5,%6,%7}, {%8,%9}, {%0,%1,%2,%3};"
                 : "+f"(c[0]), "+f"(c[1]), "+f"(c[2]), "+f"(c[3])
                 : "r"(a[0]), "r"(a[1]), "r"(a[2]), "r"(a[3]), "r"(b0), "r"(b1));
}
__device__ __forceinline__ void cp_async16(uint32_t saddr, const void* gaddr) {
    asm volatile("cp.async.cg.shared.global [%0], [%1], 16;" :: "r"(saddr), "l"(gaddr));
}
__device__ __forceinline__ void cp_commit() { asm volatile("cp.async.commit_group;"); }
__device__ __forceinline__ void cp_wait0() { asm volatile("cp.async.wait_group 0;" ::: "memory"); }
__device__ __forceinline__ void cp_wait1() { asm volatile("cp.async.wait_group 1;" ::: "memory"); }

// ---------------- prep: x -> fp16, conv1 w -> fp16 padded [co][96] ----------------
__global__ void __launch_bounds__(256) prep_kernel(const float* __restrict__ x,
                                                   const float* __restrict__ cw) {
    int i = blockIdx.x * 256 + threadIdx.x;
    if (i < 401408) g_xh[i] = __float2half(x[i]);
    if (i < 24576) {
        int co = i / 96, k = i - co * 96;
        g_wc1[i] = (k < 81) ? __float2half(cw[co * 81 + k]) : __half(0.f);
    }
}

// ---------------- conv1 via warp-MMA fp16 implicit GEMM ----------------
// C[n(204800), co(256)] = sum_k Patch[n,k(81->96)] * Wc1[co,k]
// CTA tile 128(n) x 128(co); grid (2, 1600). Single K pass (6 k16 steps).
#define C1_STRIDE 208
#define C1_A 1024
#define C1_B 27648
__global__ void __launch_bounds__(256, 2) conv1_mma_kernel(const float* __restrict__ cb) {
    extern __shared__ char smc[];
    int* s_nbase = (int*)smc;
    float* s_bias = (float*)(smc + 512);
    uint32_t sb = smem_u32(smc);

    int tid = threadIdx.x, lane = tid & 31, wid = tid >> 5;
    int co0 = blockIdx.x * 128;
    int n0 = blockIdx.y * 128;

    if (tid < 128) {
        int n = n0 + tid;
        int b = n / 400, pos = n - b * 400;
        int oh = pos / 20, ow = pos - oh * 20;
        s_nbase[tid] = b * 784 + oh * 28 + ow;
        s_bias[tid] = cb[co0 + tid];
    }

    // B fill: weights via cp.async, 12 chunks/row, 6 per thread
    {
        int row = tid >> 1;
        int cbase = (tid & 1) * 6;
#pragma unroll
        for (int q = 0; q < 6; q++) {
            int ch = cbase + q;
            cp_async16(sb + C1_B + (uint32_t)row * C1_STRIDE + (uint32_t)ch * 16,
                       g_wc1 + (size_t)(co0 + row) * 96 + ch * 8);
        }
        cp_commit();
    }
    __syncthreads();   // s_nbase ready

    // A fill: gather 9x9 patches from g_xh (scalar, L1-resident)
    {
        int row = tid >> 1, h = tid & 1;
        int base = s_nbase[row];
        __half* arow = (__half*)(smc + C1_A + (size_t)row * C1_STRIDE);
        int kh0 = h ? 5 : 0, kh1 = h ? 9 : 5;
        for (int kh = kh0; kh < kh1; kh++) {
            const __half* src = g_xh + base + kh * 28;
#pragma unroll
            for (int kw = 0; kw < 9; kw++) arow[kh * 9 + kw] = src[kw];
        }
        if (h) {
#pragma unroll
            for (int k = 81; k < 96; k++) arow[k] = __half(0.f);
        }
    }
    cp_wait0();
    __syncthreads();

    int warp_m = wid >> 1, warp_n = wid & 1;
    uint32_t a_off = C1_A + (uint32_t)(warp_m * 32 + (lane & 7) + ((lane >> 3) & 1) * 8) * C1_STRIDE
                     + (uint32_t)(lane >> 4) * 16;
    uint32_t b_off = C1_B + (uint32_t)(warp_n * 64 + (lane & 7) + ((lane >> 4) & 1) * 8) * C1_STRIDE
                     + (uint32_t)((lane >> 3) & 1) * 16;

    float acc[2][8][4];
#pragma unroll
    for (int m = 0; m < 2; m++)
#pragma unroll
        for (int nf = 0; nf < 8; nf++)
#pragma unroll
            for (int e = 0; e < 4; e++) acc[m][nf][e] = 0.f;

#pragma unroll
    for (int ks = 0; ks < 6; ks++) {
        uint32_t ko = (uint32_t)ks * 32;
        uint32_t a0[4], a1[4];
        ldsm4(a0, sb + a_off + ko);
        ldsm4(a1, sb + a_off + 16 * C1_STRIDE + ko);
#pragma unroll
        for (int jj = 0; jj < 4; jj++) {
            uint32_t bb[4];
            ldsm4(bb, sb + b_off + (uint32_t)jj * (16 * C1_STRIDE) + ko);
            mma_f16(acc[0][2 * jj],     a0, bb[0], bb[1]);
            mma_f16(acc[1][2 * jj],     a1, bb[0], bb[1]);
            mma_f16(acc[0][2 * jj + 1], a0, bb[2], bb[3]);
            mma_f16(acc[1][2 * jj + 1], a1, bb[2], bb[3]);
        }
    }

    // epilogue: bias + write half2 channel-last
    int row0 = warp_m * 32 + (lane >> 2);
#pragma unroll
    for (int m = 0; m < 2; m++) {
        int n_a = n0 + row0 + m * 16;
        int n_b = n_a + 8;
#pragma unroll
        for (int nf = 0; nf < 8; nf++) {
            int col = warp_n * 64 + nf * 8 + (lane & 3) * 2;
            float b0 = s_bias[col], b1 = s_bias[col + 1];
            __half2 ha = __floats2half2_rn(acc[m][nf][0] + b0, acc[m][nf][1] + b1);
            __half2 hb = __floats2half2_rn(acc[m][nf][2] + b0, acc[m][nf][3] + b1);
            *(__half2*)(g_yh + (size_t)n_a * 256 + co0 + col) = ha;
            *(__half2*)(g_yh + (size_t)n_b * 256 + co0 + col) = hb;
        }
    }
}

// ---------------- prim_w -> fp16, reorder k: (ci,kh,kw) -> (kh*9+kw)*256+ci ----------------
__global__ void __launch_bounds__(256) wconv_kernel(const float* __restrict__ w) {
    __shared__ __half sw[81 * 258];
    int co = blockIdx.x, tid = threadIdx.x;
    const float* src = w + (size_t)co * 20736;
    for (int i = tid; i < 20736; i += 256) {
        int ci = i / 81, rr = i - ci * 81;
        sw[rr * 258 + ci] = __float2half(src[i]);
    }
    __syncthreads();
    __half* dst = g_wf + (size_t)co * 20736;
    for (int t = tid; t < 20736; t += 256) {
        int rr = t >> 8, ci = t & 255;
        dst[t] = sw[rr * 258 + ci];
    }
}

// ---------------- conv2 via warp-MMA fp16 implicit GEMM, all-cp.async producers ----------------
#define A_STRIDE 144
#define STAGE_BYTES 36864
__global__ void __launch_bounds__(256, 2) conv2_mma_kernel(const float* __restrict__ pb) {
    extern __shared__ char smc[];
    int* s_nbase = (int*)smc;                 // [128]
    float* s_bias = (float*)(smc + 512);      // [128]
    int* s_koff = (int*)(smc + 1024);         // [324]
    char* tiles = smc + 2368;
    uint32_t sT = smem_u32(tiles);

    int tid = threadIdx.x, lane = tid & 31, wid = tid >> 5;
    int co0 = blockIdx.x * 128;
    int n0 = blockIdx.y * 128;

    if (tid < 128) {
        int n = n0 + tid;
        int b = n / 36, pos = n - b * 36;
        int oh = pos / 6, ow = pos - oh * 6;
        s_nbase[tid] = ((b * 20 + 2 * oh) * 20 + 2 * ow) * 256;
        s_bias[tid] = pb[co0 + tid];
    }
    for (int c = tid; c < 324; c += 256) {
        int khw = c >> 2;
        int kh = khw / 9, kw = khw - 9 * kh;
        s_koff[c] = (kh * 20 + kw) * 256 + (c & 3) * 64;
    }
    __syncthreads();

    int j = tid & 7;
    int rowq = tid >> 3;

    int warp_m = wid >> 1, warp_n = wid & 1;
    uint32_t a_off = (uint32_t)(warp_m * 32 + (lane & 7) + ((lane >> 3) & 1) * 8) * A_STRIDE
                     + (uint32_t)(lane >> 4) * 16;
    uint32_t b_off = 128u * A_STRIDE + (uint32_t)(warp_n * 64 + (lane & 7) + ((lane >> 4) & 1) * 8) * A_STRIDE
                     + (uint32_t)((lane >> 3) & 1) * 16;

    float acc[2][8][4];
#pragma unroll
    for (int m = 0; m < 2; m++)
#pragma unroll
        for (int nf = 0; nf < 8; nf++)
#pragma unroll
            for (int e = 0; e < 4; e++) acc[m][nf][e] = 0.f;

#define PRODUCE(sidx, cidx)                                                            \
    do {                                                                               \
        uint32_t st_ = sT + (uint32_t)(sidx) * STAGE_BYTES;                            \
        int koff_ = s_koff[(cidx)];                                                    \
        int k0_ = (cidx) * 64;                                                         \
        _Pragma("unroll")                                                              \
        for (int rr = 0; rr < 4; rr++) {                                               \
            int row = rowq + rr * 32;                                                  \
            const __half* ga = g_yh + s_nbase[row] + koff_ + j * 8;                    \
            cp_async16(st_ + (uint32_t)row * A_STRIDE + (uint32_t)j * 16, ga);         \
            const __half* gb = g_wf + (size_t)(co0 + row) * 20736 + k0_ + j * 8;       \
            cp_async16(st_ + (uint32_t)(128 + row) * A_STRIDE + (uint32_t)j * 16, gb); \
        }                                                                              \
        cp_commit();                                                                   \
    } while (0)

    PRODUCE(0, 0);

    for (int c = 0; c < 324; c++) {
        int s = c & 1;
        uint32_t stage = sT + (uint32_t)s * STAGE_BYTES;
        bool pre = (c + 1) < 324;
        if (pre) {
            PRODUCE(s ^ 1, c + 1);
            cp_wait1();
        } else {
            cp_wait0();
        }
        __syncthreads();

#pragma unroll
        for (int ks = 0; ks < 4; ks++) {
            uint32_t ko = (uint32_t)ks * 32;
            uint32_t a0[4], a1[4];
            ldsm4(a0, stage + a_off + ko);
            ldsm4(a1, stage + a_off + 16 * A_STRIDE + ko);
#pragma unroll
            for (int jj = 0; jj < 4; jj++) {
                uint32_t bb[4];
                ldsm4(bb, stage + b_off + (uint32_t)jj * (16 * A_STRIDE) + ko);
                mma_f16(acc[0][2 * jj],     a0, bb[0], bb[1]);
                mma_f16(acc[1][2 * jj],     a1, bb[0], bb[1]);
                mma_f16(acc[0][2 * jj + 1], a0, bb[2], bb[3]);
                mma_f16(acc[1][2 * jj + 1], a1, bb[2], bb[3]);
            }
        }
        __syncthreads();
    }

    int row0 = warp_m * 32 + (lane >> 2);
#pragma unroll
    for (int m = 0; m < 2; m++) {
        int r_a = row0 + m * 16;
        int n_a = n0 + r_a, n_b = n_a + 8;
        int ba = n_a / 36, pa = n_a - ba * 36;
        int bb2 = n_b / 36, pbs = n_b - bb2 * 36;
        size_t ua = (size_t)ba * 9216 + (size_t)pa * 8;
        size_t ub = (size_t)bb2 * 9216 + (size_t)pbs * 8;
#pragma unroll
        for (int nf = 0; nf < 8; nf++) {
            int col = warp_n * 64 + nf * 8 + (lane & 3) * 2;
#pragma unroll
            for (int e = 0; e < 2; e++) {
                int lc = col + e;
                int co = co0 + lc;
                float bias = s_bias[lc];
                size_t roff = (size_t)((co & 31) * 36) * 8 + (co >> 5);
                g_u[ua + roff] = acc[m][nf][e] + bias;
                g_u[ub + roff] = acc[m][nf][2 + e] + bias;
            }
        }
    }
}

// ---------------- squash u in place ----------------
__global__ void squash_kernel() {
    int idx = blockIdx.x * 256 + threadIdx.x;
    if (idx >= 512 * 1152) return;
    float4 v0 = *reinterpret_cast<float4*>(&g_u[(size_t)idx * 8]);
    float4 v1 = *reinterpret_cast<float4*>(&g_u[(size_t)idx * 8 + 4]);
    float sn = v0.x * v0.x + v0.y * v0.y + v0.z * v0.z + v0.w * v0.w +
               v1.x * v1.x + v1.y * v1.y + v1.z * v1.z + v1.w * v1.w;
    float sc = sqrtf(sn) / (1.f + sn);
    v0.x *= sc; v0.y *= sc; v0.z *= sc; v0.w *= sc;
    v1.x *= sc; v1.y *= sc; v1.z *= sc; v1.w *= sc;
    *reinterpret_cast<float4*>(&g_u[(size_t)idx * 8]) = v0;
    *reinterpret_cast<float4*>(&g_u[(size_t)idx * 8 + 4]) = v1;
}

// ---------------- priors: 4 outputs per u load (2 c x 2 o), b split over thread halves ----------------
__global__ void __launch_bounds__(256) priors_kernel(const float* __restrict__ rw) {
    int tid = threadIdx.x;
    int r0 = blockIdx.x * 16;
    int c0 = blockIdx.y * 2;
    int bh = tid >> 7, rl = (tid >> 3) & 15, op = tid & 7;

    float wr[2][2][8];
#pragma unroll
    for (int c2 = 0; c2 < 2; c2++)
#pragma unroll
        for (int o2 = 0; o2 < 2; o2++)
#pragma unroll
            for (int i = 0; i < 8; i++)
                wr[c2][o2][i] = rw[(size_t)(c0 + c2) * 147456 + (size_t)(r0 + rl) * 128 + i * 16 + op * 2 + o2];

    const float4* usrc = (const float4*)(g_u + (size_t)(r0 + rl) * 8);
    size_t poff = (size_t)(r0 + rl) * 16 + op * 2;

    for (int b = bh; b < 512; b += 2) {
        float4 u0 = __ldg(usrc + (size_t)b * 2304);
        float4 u1 = __ldg(usrc + (size_t)b * 2304 + 1);
#pragma unroll
        for (int c2 = 0; c2 < 2; c2++) {
            float a0 = u0.x * wr[c2][0][0] + u0.y * wr[c2][0][1] + u0.z * wr[c2][0][2] + u0.w * wr[c2][0][3] +
                       u1.x * wr[c2][0][4] + u1.y * wr[c2][0][5] + u1.z * wr[c2][0][6] + u1.w * wr[c2][0][7];
            float a1 = u0.x * wr[c2][1][0] + u0.y * wr[c2][1][1] + u0.z * wr[c2][1][2] + u0.w * wr[c2][1][3] +
                       u1.x * wr[c2][1][4] + u1.y * wr[c2][1][5] + u1.z * wr[c2][1][6] + u1.w * wr[c2][1][7];
            __half2 h = __floats2half2_rn(a0, a1);
            *(__half2*)(g_priors + (size_t)(b * 10 + c0 + c2) * 18432 + poff) = h;
        }
    }
}

// ---------------- routing: one block per (b,c); P kept as half2 in smem ----------------
__device__ __forceinline__ float blk_reduce_max(float v, float* red) {
#pragma unroll
    for (int s = 16; s; s >>= 1) v = fmaxf(v, __shfl_xor_sync(0xffffffffu, v, s));
    if ((threadIdx.x & 31) == 0) red[threadIdx.x >> 5] = v;
    __syncthreads();
    float r = red[0];
#pragma unroll
    for (int i = 1; i < 8; i++) r = fmaxf(r, red[i]);
    __syncthreads();
    return r;
}
__device__ __forceinline__ float blk_reduce_sum(float v, float* red) {
#pragma unroll
    for (int s = 16; s; s >>= 1) v += __shfl_xor_sync(0xffffffffu, v, s);
    if ((threadIdx.x & 31) == 0) red[threadIdx.x >> 5] = v;
    __syncthreads();
    float r = red[0];
#pragma unroll
    for (int i = 1; i < 8; i++) r += red[i];
    __syncthreads();
    return r;
}

__global__ void __launch_bounds__(256) routing_kernel() {
    extern __shared__ float sm[];
    uint32_t* P2   = (uint32_t*)sm;            // [1152*9] half2 words (pad stride 9)
    float* blog    = sm + 10368;
    float* probs   = sm + 11520;
    float2* sred   = (float2*)(sm + 12672);
    float* s_s     = sm + 13184;
    float2* v2     = (float2*)(sm + 13200);
    float* red     = sm + 13216;

    int tid = threadIdx.x;
    int b = blockIdx.x, c = blockIdx.y;
    const uint4* gp = (const uint4*)(g_priors + ((size_t)b * 10 + c) * 18432);
    for (int i = tid; i < 2304; i += 256) {
        uint4 v = __ldg(gp + i);
        int r = i >> 1, part = (i & 1) * 4;
        uint32_t* dst = &P2[r * 9 + part];
        dst[0] = v.x; dst[1] = v.y; dst[2] = v.z; dst[3] = v.w;
    }
    for (int r = tid; r < 1152; r += 256) blog[r] = 0.f;
    __syncthreads();

    int o2 = tid & 7, rg = tid >> 3;
    for (int it = 0; it < 3; it++) {
        float mx = -1e30f;
        for (int r = tid; r < 1152; r += 256) mx = fmaxf(mx, blog[r]);
        mx = blk_reduce_max(mx, red);
        float se = 0.f;
        for (int r = tid; r < 1152; r += 256) {
            float e = expf(blog[r] - mx);
            probs[r] = e;
            se += e;
        }
        se = blk_reduce_sum(se, red);
        float inv = 1.f / se;

        float2 acc = make_float2(0.f, 0.f);
        for (int r = rg; r < 1152; r += 32) {
            float2 f = __half22float2(*(__half2*)&P2[r * 9 + o2]);
            float p = probs[r];
            acc.x = fmaf(p, f.x, acc.x);
            acc.y = fmaf(p, f.y, acc.y);
        }
        sred[tid] = acc;
        __syncthreads();
        if (tid < 16) {
            int oo2 = tid >> 1, comp = tid & 1;
            float s = 0.f;
#pragma unroll
            for (int g = 0; g < 32; g++) {
                float2 t = sred[g * 8 + oo2];
                s += comp ? t.y : t.x;
            }
            s_s[tid] = s * inv;
        }
        __syncthreads();
        if (tid < 8) {
            float sn = 0.f;
#pragma unroll
            for (int oo = 0; oo < 16; oo++) sn += s_s[oo] * s_s[oo];
            float sc = sqrtf(sn) / (1.f + sn);
            v2[tid] = make_float2(s_s[2 * tid] * sc, s_s[2 * tid + 1] * sc);
            if (tid == 0 && it == 2) g_logits[b * 10 + c] = sn / (1.f + sn);
        }
        __syncthreads();
        if (it < 2) {
            for (int r = tid; r < 1152; r += 256) {
                float a = 0.f;
#pragma unroll
                for (int jj = 0; jj < 8; jj++) {
                    float2 f = __half22float2(*(__half2*)&P2[r * 9 + jj]);
                    float2 vv = v2[jj];
                    a = fmaf(f.x, vv.x, a);
                    a = fmaf(f.y, vv.y, a);
                }
                blog[r] += a;
            }
            __syncthreads();
        }
    }
}

// ---------------- final softmax over 10 classes ----------------
__global__ void final_kernel(float* __restrict__ out) {
    int b = blockIdx.x * blockDim.x + threadIdx.x;
    if (b >= 512) return;
    float l[10];
    float mx = -1e30f;
#pragma unroll
    for (int i = 0; i < 10; i++) { l[i] = g_logits[b * 10 + i]; mx = fmaxf(mx, l[i]); }
    float se = 0.f;
#pragma unroll
    for (int i = 0; i < 10; i++) { l[i] = expf(l[i] - mx); se += l[i]; }
    float inv = 1.f / se;
#pragma unroll
    for (int i = 0; i < 10; i++) out[b * 10 + i] = l[i] * inv;
}

// ---------------- launch ----------------
extern "C" void kernel_launch(void* const* d_in, const int* in_sizes, int n_in,
                              void* d_out, int out_size) {
    const float* x       = (const float*)d_in[0];
    const float* conv_w  = (const float*)d_in[1];
    const float* conv_b  = (const float*)d_in[2];
    const float* prim_w  = (const float*)d_in[3];
    const float* prim_b  = (const float*)d_in[4];
    const float* route_w = (const float*)d_in[5];
    float* out = (float*)d_out;

    prep_kernel<<<1568, 256>>>(x, conv_w);
    wconv_kernel<<<256, 256>>>(prim_w);
    cudaFuncSetAttribute(conv1_mma_kernel, cudaFuncAttributeMaxDynamicSharedMemorySize, 54528);
    conv1_mma_kernel<<<dim3(2, 1600), 256, 54528>>>(conv_b);
    cudaFuncSetAttribute(conv2_mma_kernel, cudaFuncAttributeMaxDynamicSharedMemorySize, 76096);
    conv2_mma_kernel<<<dim3(2, 144), 256, 76096>>>(prim_b);
    squash_kernel<<<2304, 256>>>();
    priors_kernel<<<dim3(72, 5), 256>>>(route_w);
    cudaFuncSetAttribute(routing_kernel, cudaFuncAttributeMaxDynamicSharedMemorySize, 52896);
    routing_kernel<<<dim3(512, 10), 256, 52896>>>();
    final_kernel<<<2, 256>>>(out);
}